// round 1
// baseline (speedup 1.0000x reference)
#include <cuda_runtime.h>
#include <math.h>

// ---------------- problem constants ----------------
#define NPATCH 500      // N = T/P
#define DMODEL 512
#define NHS    5        // heads per scale
#define KDIM   32
#define QKVD   160      // NHS*KDIM
#define CATD   1536     // 3 scales * D
#define FFD    2048
#define NLAYER 6
#define NBATCH 32
#define NCLS   256
#define LN_EPS 1e-3f

// ---------------- scratch (static, no allocs) ----------------
__device__ float d_h   [NPATCH * DMODEL];
__device__ float d_pool[(NPATCH/2) * DMODEL];
__device__ float d_q   [NPATCH * QKVD];
__device__ float d_k   [NPATCH * QKVD];
__device__ float d_v   [NPATCH * QKVD];
__device__ float d_o   [NPATCH * QKVD];
__device__ float d_cat [NPATCH * CATD];
__device__ float d_ff  [NPATCH * FFD];
__device__ float d_t2  [NPATCH * DMODEL];
__device__ float d_cs  [DMODEL];
__device__ float d_gv  [DMODEL];

// ---------------- kernels ----------------

// column sum of patch_W (100 x 512)
__global__ void colsum_kernel(const float* __restrict__ W, float* __restrict__ cs) {
    int d = threadIdx.x;
    float s = 0.f;
    #pragma unroll 4
    for (int p = 0; p < 100; p++) s += W[p * DMODEL + d];
    cs[d] = s;
}

// h0[n,d] = ln_in_b * colsum(patch_W)[d] + patch_b[d] + pos_emb[n,d]
__global__ void init_h_kernel(const float* __restrict__ cs, const float* __restrict__ ln_in_b,
                              const float* __restrict__ patch_b, const float* __restrict__ pos,
                              float* __restrict__ h) {
    int n = blockIdx.x, d = threadIdx.x;
    h[n * DMODEL + d] = ln_in_b[0] * cs[d] + patch_b[d] + pos[n * DMODEL + d];
}

// avg pool over s consecutive rows
__global__ void pool_kernel(const float* __restrict__ h, float* __restrict__ out, int s) {
    int i = blockIdx.x, d = threadIdx.x;
    float acc = 0.f;
    for (int j = 0; j < s; j++) acc += h[(i * s + j) * DMODEL + d];
    out[i * DMODEL + d] = acc / (float)s;
}

// cat[n, si*512 + d] = a[n/s, d]   (repeat upsample + concat)
__global__ void upsample_kernel(const float* __restrict__ a, float* __restrict__ cat, int s, int si) {
    int n = blockIdx.x, d = threadIdx.x;
    cat[n * CATD + si * DMODEL + d] = a[(n / s) * DMODEL + d];
}

// Tiled fp32 GEMM: C[M,N] = A[M,K] @ B[K,N] + bias[N].  K % 16 == 0 required.
__global__ void gemm_bias_kernel(const float* __restrict__ A, const float* __restrict__ B,
                                 const float* __restrict__ bias, float* __restrict__ C,
                                 int M, int N, int K) {
    __shared__ float As[16][65];  // [k][m]
    __shared__ float Bs[16][65];  // [k][n]
    const int tid = threadIdx.x;            // 256 threads
    const int tm = (tid / 16) * 4;
    const int tn = (tid % 16) * 4;
    const int bM = blockIdx.y * 64;
    const int bN = blockIdx.x * 64;

    float acc[4][4] = {};
    for (int k0 = 0; k0 < K; k0 += 16) {
        #pragma unroll
        for (int i = tid; i < 64 * 16; i += 256) {
            int m = i / 16, kk = i % 16;
            int gm = bM + m;
            As[kk][m] = (gm < M) ? A[(size_t)gm * K + k0 + kk] : 0.f;
        }
        #pragma unroll
        for (int i = tid; i < 16 * 64; i += 256) {
            int kk = i / 64, n = i % 64;
            int gn = bN + n;
            Bs[kk][n] = (gn < N) ? B[(size_t)(k0 + kk) * N + gn] : 0.f;
        }
        __syncthreads();
        #pragma unroll
        for (int kk = 0; kk < 16; kk++) {
            float a[4], b[4];
            #pragma unroll
            for (int i = 0; i < 4; i++) a[i] = As[kk][tm + i];
            #pragma unroll
            for (int j = 0; j < 4; j++) b[j] = Bs[kk][tn + j];
            #pragma unroll
            for (int i = 0; i < 4; i++)
                #pragma unroll
                for (int j = 0; j < 4; j++)
                    acc[i][j] += a[i] * b[j];
        }
        __syncthreads();
    }
    #pragma unroll
    for (int i = 0; i < 4; i++) {
        int gm = bM + tm + i;
        if (gm >= M) continue;
        #pragma unroll
        for (int j = 0; j < 4; j++) {
            int gn = bN + tn + j;
            if (gn < N) C[(size_t)gm * N + gn] = acc[i][j] + bias[gn];
        }
    }
}

// Flash-style attention: one warp per (query n, head h). KD=32 -> one lane per dim.
__global__ void attn_kernel(const float* __restrict__ q, const float* __restrict__ k,
                            const float* __restrict__ v, float* __restrict__ o, int Ns) {
    int warp = blockIdx.x * (blockDim.x / 32) + threadIdx.x / 32;
    int lane = threadIdx.x & 31;
    int total = Ns * NHS;
    if (warp >= total) return;
    int n = warp / NHS, h = warp % NHS;
    const float scale = 0.1767766952966369f;  // 1/sqrt(32)
    float qv = q[n * QKVD + h * KDIM + lane] * scale;
    float mmax = -INFINITY, ssum = 0.f, oacc = 0.f;
    for (int m = 0; m < Ns; m++) {
        float s = qv * k[m * QKVD + h * KDIM + lane];
        #pragma unroll
        for (int off = 16; off; off >>= 1) s += __shfl_xor_sync(0xffffffffu, s, off);
        float nm = fmaxf(mmax, s);
        float corr = __expf(mmax - nm);       // exp(-inf)=0 handles first iter
        float p = __expf(s - nm);
        ssum = ssum * corr + p;
        oacc = oacc * corr + p * v[m * QKVD + h * KDIM + lane];
        mmax = nm;
    }
    o[n * QKVD + h * KDIM + lane] = oacc / ssum;
}

// h[n,:] = LayerNorm(h[n,:] + add[n,:]) * g + b   (256 threads/row, D=512)
__global__ void add_ln_kernel(float* __restrict__ h, const float* __restrict__ add,
                              const float* __restrict__ g, const float* __restrict__ b) {
    int n = blockIdx.x, t = threadIdx.x;
    __shared__ float red[8];
    __shared__ float stat;
    float v0 = h[n * DMODEL + t]       + add[n * DMODEL + t];
    float v1 = h[n * DMODEL + t + 256] + add[n * DMODEL + t + 256];

    // mean
    float s = v0 + v1;
    #pragma unroll
    for (int o = 16; o; o >>= 1) s += __shfl_xor_sync(0xffffffffu, s, o);
    if ((t & 31) == 0) red[t >> 5] = s;
    __syncthreads();
    if (t < 32) {
        float x = (t < 8) ? red[t] : 0.f;
        #pragma unroll
        for (int o = 4; o; o >>= 1) x += __shfl_xor_sync(0xffffffffu, x, o);
        if (t == 0) stat = x / (float)DMODEL;
    }
    __syncthreads();
    float mean = stat;
    float dd0 = v0 - mean, dd1 = v1 - mean;

    // var
    __syncthreads();
    float vs = dd0 * dd0 + dd1 * dd1;
    #pragma unroll
    for (int o = 16; o; o >>= 1) vs += __shfl_xor_sync(0xffffffffu, vs, o);
    if ((t & 31) == 0) red[t >> 5] = vs;
    __syncthreads();
    if (t < 32) {
        float x = (t < 8) ? red[t] : 0.f;
        #pragma unroll
        for (int o = 4; o; o >>= 1) x += __shfl_xor_sync(0xffffffffu, x, o);
        if (t == 0) stat = rsqrtf(x / (float)DMODEL + LN_EPS);
    }
    __syncthreads();
    float rstd = stat;
    h[n * DMODEL + t]       = dd0 * rstd * g[t]       + b[t];
    h[n * DMODEL + t + 256] = dd1 * rstd * g[t + 256] + b[t + 256];
}

// exact GELU (erf), elementwise in-place
__global__ void gelu_kernel(float* __restrict__ x, int n) {
    int i = blockIdx.x * blockDim.x + threadIdx.x;
    if (i < n) {
        float v = x[i];
        x[i] = 0.5f * v * (1.f + erff(v * 0.70710678118654752f));
    }
}

// g[d] = mean over 500 rows of h
__global__ void gpool_kernel(const float* __restrict__ h, float* __restrict__ g) {
    int d = threadIdx.x;
    float s = 0.f;
    for (int n = 0; n < NPATCH; n++) s += h[n * DMODEL + d];
    g[d] = s / (float)NPATCH;
}

// logits = g @ head_W + head_b ; softmax ; broadcast to 32 batch rows
__global__ void head_kernel(const float* __restrict__ g, const float* __restrict__ W,
                            const float* __restrict__ b, float* __restrict__ out) {
    __shared__ float gs[DMODEL];
    __shared__ float red[8];
    __shared__ float stat;
    int t = threadIdx.x;  // 256
    gs[t] = g[t]; gs[t + 256] = g[t + 256];
    __syncthreads();
    float acc = b[t];
    #pragma unroll 4
    for (int d = 0; d < DMODEL; d++) acc += gs[d] * W[d * NCLS + t];

    // max
    float m = acc;
    #pragma unroll
    for (int o = 16; o; o >>= 1) m = fmaxf(m, __shfl_xor_sync(0xffffffffu, m, o));
    if ((t & 31) == 0) red[t >> 5] = m;
    __syncthreads();
    if (t < 32) {
        float x = (t < 8) ? red[t] : -INFINITY;
        #pragma unroll
        for (int o = 4; o; o >>= 1) x = fmaxf(x, __shfl_xor_sync(0xffffffffu, x, o));
        if (t == 0) stat = x;
    }
    __syncthreads();
    float e = expf(acc - stat);
    __syncthreads();
    float s = e;
    #pragma unroll
    for (int o = 16; o; o >>= 1) s += __shfl_xor_sync(0xffffffffu, s, o);
    if ((t & 31) == 0) red[t >> 5] = s;
    __syncthreads();
    if (t < 32) {
        float x = (t < 8) ? red[t] : 0.f;
        #pragma unroll
        for (int o = 4; o; o >>= 1) x += __shfl_xor_sync(0xffffffffu, x, o);
        if (t == 0) stat = x;
    }
    __syncthreads();
    float p = e / stat;
    for (int bb = 0; bb < NBATCH; bb++) out[bb * NCLS + t] = p;
}

// ---------------- host launcher ----------------
static inline void gemm(const float* A, const float* B, const float* bias, float* C,
                        int M, int N, int K) {
    dim3 grid((N + 63) / 64, (M + 63) / 64);
    gemm_bias_kernel<<<grid, 256>>>(A, B, bias, C, M, N, K);
}

extern "C" void kernel_launch(void* const* d_in, const int* in_sizes, int n_in,
                              void* d_out, int out_size) {
    // metadata order (setup_inputs dict order)
    const float* ln_in_b = (const float*)d_in[2];
    const float* patch_W = (const float*)d_in[3];
    const float* patch_b = (const float*)d_in[4];
    const float* pos_emb = (const float*)d_in[5];
    const float* Wq = (const float*)d_in[6];
    const float* bq = (const float*)d_in[7];
    const float* Wk = (const float*)d_in[8];
    const float* bk = (const float*)d_in[9];
    const float* Wv = (const float*)d_in[10];
    const float* bv = (const float*)d_in[11];
    const float* Wo = (const float*)d_in[12];
    const float* bo = (const float*)d_in[13];
    const float* Wc = (const float*)d_in[14];
    const float* bc = (const float*)d_in[15];
    const float* ln1_g = (const float*)d_in[16];
    const float* ln1_b = (const float*)d_in[17];
    const float* W1 = (const float*)d_in[18];
    const float* b1 = (const float*)d_in[19];
    const float* W2 = (const float*)d_in[20];
    const float* b2 = (const float*)d_in[21];
    const float* ln2_g = (const float*)d_in[22];
    const float* ln2_b = (const float*)d_in[23];
    const float* head_W = (const float*)d_in[24];
    const float* head_b = (const float*)d_in[25];
    float* out = (float*)d_out;

    float *hp, *pp, *qp, *kp, *vp, *op, *catp, *ffp, *t2p, *csp, *gp;
    cudaGetSymbolAddress((void**)&hp,  d_h);
    cudaGetSymbolAddress((void**)&pp,  d_pool);
    cudaGetSymbolAddress((void**)&qp,  d_q);
    cudaGetSymbolAddress((void**)&kp,  d_k);
    cudaGetSymbolAddress((void**)&vp,  d_v);
    cudaGetSymbolAddress((void**)&op,  d_o);
    cudaGetSymbolAddress((void**)&catp, d_cat);
    cudaGetSymbolAddress((void**)&ffp, d_ff);
    cudaGetSymbolAddress((void**)&t2p, d_t2);
    cudaGetSymbolAddress((void**)&csp, d_cs);
    cudaGetSymbolAddress((void**)&gp,  d_gv);

    // h0: degenerate size-1 LN makes patches constant = ln_in_b
    colsum_kernel<<<1, DMODEL>>>(patch_W, csp);
    init_h_kernel<<<NPATCH, DMODEL>>>(csp, ln_in_b, patch_b, pos_emb, hp);

    const int scales[3] = {1, 2, 4};
    for (int l = 0; l < NLAYER; l++) {
        for (int si = 0; si < 3; si++) {
            int s = scales[si];
            int Ns = NPATCH / s;
            const float* A = hp;
            if (s > 1) { pool_kernel<<<Ns, DMODEL>>>(hp, pp, s); A = pp; }
            size_t wo  = ((size_t)l * 3 + si) * DMODEL * QKVD;   // Wq/Wk/Wv slice
            size_t bqo = ((size_t)l * 3 + si) * QKVD;
            gemm(A, Wq + wo, bq + bqo, qp, Ns, QKVD, DMODEL);
            gemm(A, Wk + wo, bk + bqo, kp, Ns, QKVD, DMODEL);
            gemm(A, Wv + wo, bv + bqo, vp, Ns, QKVD, DMODEL);
            int warps = Ns * NHS;
            attn_kernel<<<(warps + 7) / 8, 256>>>(qp, kp, vp, op, Ns);
            size_t woo = ((size_t)l * 3 + si) * QKVD * DMODEL;   // Wo slice (160x512)
            size_t boo = ((size_t)l * 3 + si) * DMODEL;
            gemm(op, Wo + woo, bo + boo, t2p, Ns, DMODEL, QKVD);
            upsample_kernel<<<NPATCH, DMODEL>>>(t2p, catp, s, si);
        }
        // combine
        gemm(catp, Wc + (size_t)l * CATD * DMODEL, bc + (size_t)l * DMODEL, t2p,
             NPATCH, DMODEL, CATD);
        add_ln_kernel<<<NPATCH, 256>>>(hp, t2p, ln1_g + l * DMODEL, ln1_b + l * DMODEL);
        // FFN
        gemm(hp, W1 + (size_t)l * DMODEL * FFD, b1 + (size_t)l * FFD, ffp,
             NPATCH, FFD, DMODEL);
        gelu_kernel<<<(NPATCH * FFD + 255) / 256, 256>>>(ffp, NPATCH * FFD);
        gemm(ffp, W2 + (size_t)l * FFD * DMODEL, b2 + (size_t)l * DMODEL, t2p,
             NPATCH, DMODEL, FFD);
        add_ln_kernel<<<NPATCH, 256>>>(hp, t2p, ln2_g + l * DMODEL, ln2_b + l * DMODEL);
    }

    gpool_kernel<<<1, DMODEL>>>(hp, gp);
    head_kernel<<<1, NCLS>>>(gp, head_W, head_b, out);
}

// round 2
// speedup vs baseline: 6.2316x; 6.2316x over previous
#include <cuda_runtime.h>
#include <cstdint>
#include <math.h>

// ---------------- problem constants ----------------
#define NPATCH 500
#define DMODEL 512
#define NHS    5
#define KDIM   32
#define QKVD   160
#define CATD   1536
#define FFD    2048
#define NLAYER 6
#define NBATCH 32
#define NCLS   256
#define LN_EPS 1e-3f

#define BM 32
#define BN 64
#define BK 16
#define APAD 20

// rows for 3 scales packed: scale1 rows [0,500), scale2 [500,750), scale4 [750,875)
#define RTOT 875

// ---------------- scratch ----------------
__device__ float d_h   [NPATCH * DMODEL];
__device__ float d_pool[375 * DMODEL];        // rows 0..249: pool2, 250..374: pool4
__device__ float d_q   [RTOT * QKVD];
__device__ float d_k   [RTOT * QKVD];
__device__ float d_v   [RTOT * QKVD];
__device__ float d_o   [RTOT * QKVD];
__device__ float d_ao  [RTOT * DMODEL];
__device__ float d_cat [NPATCH * CATD];
__device__ float d_ff  [NPATCH * FFD];
__device__ float d_t2  [NPATCH * DMODEL];
__device__ float d_cs  [DMODEL];
__device__ float d_gv  [DMODEL];

// ---------------- ptx helpers ----------------
__device__ __forceinline__ uint32_t smem_u32(const void* p) {
    return (uint32_t)__cvta_generic_to_shared(p);
}
__device__ __forceinline__ void cp16(uint32_t dst, const void* src, int sbytes) {
    asm volatile("cp.async.cg.shared.global [%0], [%1], 16, %2;\n"
                 :: "r"(dst), "l"(src), "r"(sbytes));
}
__device__ __forceinline__ void cp_commit() { asm volatile("cp.async.commit_group;\n"); }
__device__ __forceinline__ unsigned long long pack2(float x, float y) {
    unsigned long long r;
    asm("mov.b64 %0, {%1, %2};" : "=l"(r) : "f"(x), "f"(y));
    return r;
}
__device__ __forceinline__ void unpack2(unsigned long long v, float& x, float& y) {
    asm("mov.b64 {%0, %1}, %2;" : "=f"(x), "=f"(y) : "l"(v));
}
__device__ __forceinline__ void fma2(unsigned long long& d, unsigned long long a,
                                     unsigned long long b) {
    asm("fma.rn.f32x2 %0, %1, %2, %0;" : "+l"(d) : "l"(a), "l"(b));
}
__device__ __forceinline__ float gelu_f(float x) {
    return 0.5f * x * (1.f + erff(x * 0.70710678118654752f));
}

// ---------------- core GEMM tile (cp.async double-buffered, f32x2 FMA) ----------------
// C[M,N] = A[M,K] @ B[K,N] + bias ; act==1 applies exact GELU.
// Requires: K % 16 == 0, N % 4 == 0. 128 threads.
__device__ __forceinline__ void gemm_tile(
    const float* __restrict__ A, const float* __restrict__ B,
    const float* __restrict__ bias, float* __restrict__ C,
    int M, int N, int K, int bM, int bN, int act)
{
    __shared__ float As[2][BM][APAD];
    __shared__ float Bs[2][BK][BN];
    const int tid = threadIdx.x;

    const int ar = tid >> 2;           // 0..31
    const int ac = (tid & 3) * 4;      // 0..12
    const int br = tid >> 4;           // 0..7 (two chunks: br, br+8)
    const int bc = (tid & 15) * 4;     // 0..60

    const int gmA = bM + ar;
    const int aBytes = (gmA < M) ? 16 : 0;
    const float* aSrc = A + (size_t)gmA * K + ac;

    const int gnB = bN + bc;
    const int bBytes = (gnB < N) ? 16 : 0;
    const float* bSrc0 = B + (size_t)br * N + gnB;
    const float* bSrc1 = B + (size_t)(br + 8) * N + gnB;

    uint32_t aDst[2], bDst0[2], bDst1[2];
    aDst[0]  = smem_u32(&As[0][ar][ac]);   aDst[1]  = smem_u32(&As[1][ar][ac]);
    bDst0[0] = smem_u32(&Bs[0][br][bc]);   bDst0[1] = smem_u32(&Bs[1][br][bc]);
    bDst1[0] = smem_u32(&Bs[0][br+8][bc]); bDst1[1] = smem_u32(&Bs[1][br+8][bc]);

    const int T = K / BK;

    // prologue: tile 0 -> buffer 0
    cp16(aDst[0], aSrc, aBytes);
    cp16(bDst0[0], bSrc0, bBytes);
    cp16(bDst1[0], bSrc1, bBytes);
    cp_commit();

    const int tm = (tid >> 4) * 4;     // 0..28
    const int tn = (tid & 15) * 4;     // 0..60
    unsigned long long acc[4][2] = {};

    for (int t = 0; t < T; ++t) {
        const int cur = t & 1;
        if (t + 1 < T) {
            const int nxt = cur ^ 1;
            const int k0 = (t + 1) * BK;
            cp16(aDst[nxt], aSrc + k0, aBytes);
            cp16(bDst0[nxt], bSrc0 + (size_t)k0 * N, bBytes);
            cp16(bDst1[nxt], bSrc1 + (size_t)k0 * N, bBytes);
            cp_commit();
            asm volatile("cp.async.wait_group 1;\n");
        } else {
            asm volatile("cp.async.wait_group 0;\n");
        }
        __syncthreads();
        #pragma unroll
        for (int kk = 0; kk < BK; ++kk) {
            float4 b4 = *(const float4*)(&Bs[cur][kk][tn]);
            unsigned long long b01 = pack2(b4.x, b4.y);
            unsigned long long b23 = pack2(b4.z, b4.w);
            #pragma unroll
            for (int i = 0; i < 4; ++i) {
                float a = As[cur][tm + i][kk];
                unsigned long long aa = pack2(a, a);
                fma2(acc[i][0], aa, b01);
                fma2(acc[i][1], aa, b23);
            }
        }
        __syncthreads();
    }

    // epilogue
    const int col = bN + tn;
    if (col < N) {
        float4 bb = *(const float4*)(bias + col);
        #pragma unroll
        for (int i = 0; i < 4; ++i) {
            int row = bM + tm + i;
            if (row >= M) continue;
            float c0, c1, c2, c3;
            unpack2(acc[i][0], c0, c1);
            unpack2(acc[i][1], c2, c3);
            c0 += bb.x; c1 += bb.y; c2 += bb.z; c3 += bb.w;
            if (act == 1) {
                c0 = gelu_f(c0); c1 = gelu_f(c1); c2 = gelu_f(c2); c3 = gelu_f(c3);
            }
            float4 o4 = make_float4(c0, c1, c2, c3);
            *(float4*)(C + (size_t)row * N + col) = o4;
        }
    }
}

// ---------------- GEMM wrappers ----------------
__global__ void __launch_bounds__(128) gemm_single(
    const float* __restrict__ A, const float* __restrict__ B,
    const float* __restrict__ bias, float* __restrict__ C,
    int M, int N, int K, int act)
{
    int bM = blockIdx.y * BM;
    if (bM >= M) return;
    gemm_tile(A, B, bias, C, M, N, K, bM, blockIdx.x * BN, act);
}

__constant__ int c_Ms[3] = {500, 250, 125};
__constant__ int c_ro[3] = {0, 500, 750};

// z = si*3 + which(0=q,1=k,2=v). W*/b* are layer-base pointers.
__global__ void __launch_bounds__(128) gemm_qkv(
    const float* __restrict__ h, const float* __restrict__ pool,
    const float* __restrict__ Wq, const float* __restrict__ Wk, const float* __restrict__ Wv,
    const float* __restrict__ bq, const float* __restrict__ bk, const float* __restrict__ bv,
    float* __restrict__ q, float* __restrict__ k, float* __restrict__ v)
{
    int z = blockIdx.z;
    int si = z / 3, which = z - si * 3;
    int M = c_Ms[si];
    int bM = blockIdx.y * BM;
    if (bM >= M) return;
    const float* A = (si == 0) ? h : (pool + (si == 2 ? 250 * DMODEL : 0));
    const float* W = (which == 0) ? Wq : (which == 1) ? Wk : Wv;
    const float* bb = (which == 0) ? bq : (which == 1) ? bk : bv;
    float* Cb = (which == 0) ? q : (which == 1) ? k : v;
    gemm_tile(A, W + (size_t)si * DMODEL * QKVD, bb + (size_t)si * QKVD,
              Cb + (size_t)c_ro[si] * QKVD, M, QKVD, DMODEL, bM, blockIdx.x * BN, 0);
}

__global__ void __launch_bounds__(128) gemm_wo(
    const float* __restrict__ o, const float* __restrict__ Wo,
    const float* __restrict__ bo, float* __restrict__ ao)
{
    int si = blockIdx.z;
    int M = c_Ms[si];
    int bM = blockIdx.y * BM;
    if (bM >= M) return;
    gemm_tile(o + (size_t)c_ro[si] * QKVD, Wo + (size_t)si * QKVD * DMODEL,
              bo + (size_t)si * DMODEL, ao + (size_t)c_ro[si] * DMODEL,
              M, DMODEL, QKVD, bM, blockIdx.x * BN, 0);
}

// ---------------- small kernels ----------------
__global__ void colsum_kernel(const float* __restrict__ W, float* __restrict__ cs) {
    int d = threadIdx.x;
    float s = 0.f;
    #pragma unroll 4
    for (int p = 0; p < 100; p++) s += W[p * DMODEL + d];
    cs[d] = s;
}

__global__ void init_h_kernel(const float* __restrict__ cs, const float* __restrict__ ln_in_b,
                              const float* __restrict__ patch_b, const float* __restrict__ pos,
                              float* __restrict__ h) {
    int n = blockIdx.x, d = threadIdx.x;
    h[n * DMODEL + d] = ln_in_b[0] * cs[d] + patch_b[d] + pos[n * DMODEL + d];
}

// rows 0..249: avg of 2 ; rows 250..374: avg of 4
__global__ void pool_kernel(const float* __restrict__ h, float* __restrict__ p) {
    int i = blockIdx.x, d = threadIdx.x;
    if (i < 250) {
        p[i * DMODEL + d] = 0.5f * (h[(2 * i) * DMODEL + d] + h[(2 * i + 1) * DMODEL + d]);
    } else {
        int j = i - 250;
        p[i * DMODEL + d] = 0.25f * (h[(4 * j) * DMODEL + d] + h[(4 * j + 1) * DMODEL + d] +
                                     h[(4 * j + 2) * DMODEL + d] + h[(4 * j + 3) * DMODEL + d]);
    }
}

// all scales in one launch; warp per (scale,query,head)
__global__ void attn_kernel(const float* __restrict__ q, const float* __restrict__ k,
                            const float* __restrict__ v, float* __restrict__ o) {
    int w = blockIdx.x * 8 + (threadIdx.x >> 5);
    int lane = threadIdx.x & 31;
    if (w >= 4375) return;
    int base, Ns, ro;
    if (w < 2500)      { base = 0;    Ns = 500; ro = 0; }
    else if (w < 3750) { base = 2500; Ns = 250; ro = 500; }
    else               { base = 3750; Ns = 125; ro = 750; }
    int local = w - base;
    int n = local / 5, h = local - n * 5;
    const float scale = 0.1767766952966369f;  // 1/sqrt(32)
    float qv = q[(size_t)(ro + n) * QKVD + h * KDIM + lane] * scale;
    const float* kp = k + (size_t)ro * QKVD + h * KDIM + lane;
    const float* vp = v + (size_t)ro * QKVD + h * KDIM + lane;
    float mmax = -INFINITY, ssum = 0.f, oacc = 0.f;
    for (int m = 0; m < Ns; m++) {
        float s = qv * kp[(size_t)m * QKVD];
        #pragma unroll
        for (int off = 16; off; off >>= 1) s += __shfl_xor_sync(0xffffffffu, s, off);
        float nm = fmaxf(mmax, s);
        float corr = __expf(mmax - nm);
        float p = __expf(s - nm);
        ssum = ssum * corr + p;
        oacc = oacc * corr + p * vp[(size_t)m * QKVD];
        mmax = nm;
    }
    o[(size_t)(ro + n) * QKVD + h * KDIM + lane] = oacc / ssum;
}

// concat + repeat-upsample all 3 scales
__global__ void cat_kernel(const float* __restrict__ ao, float* __restrict__ cat) {
    int n = blockIdx.x, d = threadIdx.x;
    cat[n * CATD + d]        = ao[n * DMODEL + d];
    cat[n * CATD + 512 + d]  = ao[(500 + (n >> 1)) * DMODEL + d];
    cat[n * CATD + 1024 + d] = ao[(750 + (n >> 2)) * DMODEL + d];
}

__global__ void add_ln_kernel(float* __restrict__ h, const float* __restrict__ add,
                              const float* __restrict__ g, const float* __restrict__ b) {
    int n = blockIdx.x, t = threadIdx.x;
    __shared__ float red[8];
    __shared__ float stat;
    float v0 = h[n * DMODEL + t]       + add[n * DMODEL + t];
    float v1 = h[n * DMODEL + t + 256] + add[n * DMODEL + t + 256];

    float s = v0 + v1;
    #pragma unroll
    for (int o = 16; o; o >>= 1) s += __shfl_xor_sync(0xffffffffu, s, o);
    if ((t & 31) == 0) red[t >> 5] = s;
    __syncthreads();
    if (t < 32) {
        float x = (t < 8) ? red[t] : 0.f;
        #pragma unroll
        for (int o = 4; o; o >>= 1) x += __shfl_xor_sync(0xffffffffu, x, o);
        if (t == 0) stat = x / (float)DMODEL;
    }
    __syncthreads();
    float mean = stat;
    float dd0 = v0 - mean, dd1 = v1 - mean;

    __syncthreads();
    float vs = dd0 * dd0 + dd1 * dd1;
    #pragma unroll
    for (int o = 16; o; o >>= 1) vs += __shfl_xor_sync(0xffffffffu, vs, o);
    if ((t & 31) == 0) red[t >> 5] = vs;
    __syncthreads();
    if (t < 32) {
        float x = (t < 8) ? red[t] : 0.f;
        #pragma unroll
        for (int o = 4; o; o >>= 1) x += __shfl_xor_sync(0xffffffffu, x, o);
        if (t == 0) stat = rsqrtf(x / (float)DMODEL + LN_EPS);
    }
    __syncthreads();
    float rstd = stat;
    h[n * DMODEL + t]       = dd0 * rstd * g[t]       + b[t];
    h[n * DMODEL + t + 256] = dd1 * rstd * g[t + 256] + b[t + 256];
}

__global__ void gpool_kernel(const float* __restrict__ h, float* __restrict__ g) {
    int d = threadIdx.x;
    float s = 0.f;
    for (int n = 0; n < NPATCH; n++) s += h[n * DMODEL + d];
    g[d] = s / (float)NPATCH;
}

__global__ void head_kernel(const float* __restrict__ g, const float* __restrict__ W,
                            const float* __restrict__ b, float* __restrict__ out) {
    __shared__ float gs[DMODEL];
    __shared__ float red[8];
    __shared__ float stat;
    int t = threadIdx.x;
    gs[t] = g[t]; gs[t + 256] = g[t + 256];
    __syncthreads();
    float acc = b[t];
    #pragma unroll 4
    for (int d = 0; d < DMODEL; d++) acc += gs[d] * W[d * NCLS + t];

    float m = acc;
    #pragma unroll
    for (int o = 16; o; o >>= 1) m = fmaxf(m, __shfl_xor_sync(0xffffffffu, m, o));
    if ((t & 31) == 0) red[t >> 5] = m;
    __syncthreads();
    if (t < 32) {
        float x = (t < 8) ? red[t] : -INFINITY;
        #pragma unroll
        for (int o = 4; o; o >>= 1) x = fmaxf(x, __shfl_xor_sync(0xffffffffu, x, o));
        if (t == 0) stat = x;
    }
    __syncthreads();
    float e = expf(acc - stat);
    __syncthreads();
    float s = e;
    #pragma unroll
    for (int o = 16; o; o >>= 1) s += __shfl_xor_sync(0xffffffffu, s, o);
    if ((t & 31) == 0) red[t >> 5] = s;
    __syncthreads();
    if (t < 32) {
        float x = (t < 8) ? red[t] : 0.f;
        #pragma unroll
        for (int o = 4; o; o >>= 1) x += __shfl_xor_sync(0xffffffffu, x, o);
        if (t == 0) stat = x;
    }
    __syncthreads();
    float p = e / stat;
    for (int bb = 0; bb < NBATCH; bb++) out[bb * NCLS + t] = p;
}

// ---------------- host launcher ----------------
extern "C" void kernel_launch(void* const* d_in, const int* in_sizes, int n_in,
                              void* d_out, int out_size) {
    const float* ln_in_b = (const float*)d_in[2];
    const float* patch_W = (const float*)d_in[3];
    const float* patch_b = (const float*)d_in[4];
    const float* pos_emb = (const float*)d_in[5];
    const float* Wq = (const float*)d_in[6];
    const float* bq = (const float*)d_in[7];
    const float* Wk = (const float*)d_in[8];
    const float* bk = (const float*)d_in[9];
    const float* Wv = (const float*)d_in[10];
    const float* bv = (const float*)d_in[11];
    const float* Wo = (const float*)d_in[12];
    const float* bo = (const float*)d_in[13];
    const float* Wc = (const float*)d_in[14];
    const float* bc = (const float*)d_in[15];
    const float* ln1_g = (const float*)d_in[16];
    const float* ln1_b = (const float*)d_in[17];
    const float* W1 = (const float*)d_in[18];
    const float* b1 = (const float*)d_in[19];
    const float* W2 = (const float*)d_in[20];
    const float* b2 = (const float*)d_in[21];
    const float* ln2_g = (const float*)d_in[22];
    const float* ln2_b = (const float*)d_in[23];
    const float* head_W = (const float*)d_in[24];
    const float* head_b = (const float*)d_in[25];
    float* out = (float*)d_out;

    float *hp, *pp, *qp, *kp, *vp, *op, *aop, *catp, *ffp, *t2p, *csp, *gp;
    cudaGetSymbolAddress((void**)&hp,  d_h);
    cudaGetSymbolAddress((void**)&pp,  d_pool);
    cudaGetSymbolAddress((void**)&qp,  d_q);
    cudaGetSymbolAddress((void**)&kp,  d_k);
    cudaGetSymbolAddress((void**)&vp,  d_v);
    cudaGetSymbolAddress((void**)&op,  d_o);
    cudaGetSymbolAddress((void**)&aop, d_ao);
    cudaGetSymbolAddress((void**)&catp, d_cat);
    cudaGetSymbolAddress((void**)&ffp, d_ff);
    cudaGetSymbolAddress((void**)&t2p, d_t2);
    cudaGetSymbolAddress((void**)&csp, d_cs);
    cudaGetSymbolAddress((void**)&gp,  d_gv);

    colsum_kernel<<<1, DMODEL>>>(patch_W, csp);
    init_h_kernel<<<NPATCH, DMODEL>>>(csp, ln_in_b, patch_b, pos_emb, hp);

    for (int l = 0; l < NLAYER; l++) {
        size_t wqkv = (size_t)l * 3 * DMODEL * QKVD;
        size_t bqkv = (size_t)l * 3 * QKVD;
        size_t wwo  = (size_t)l * 3 * QKVD * DMODEL;
        size_t bwo  = (size_t)l * 3 * DMODEL;

        pool_kernel<<<375, DMODEL>>>(hp, pp);
        gemm_qkv<<<dim3(3, 16, 9), 128>>>(hp, pp,
            Wq + wqkv, Wk + wqkv, Wv + wqkv, bq + bqkv, bk + bqkv, bv + bqkv,
            qp, kp, vp);
        attn_kernel<<<547, 256>>>(qp, kp, vp, op);
        gemm_wo<<<dim3(8, 16, 3), 128>>>(op, Wo + wwo, bo + bwo, aop);
        cat_kernel<<<NPATCH, DMODEL>>>(aop, catp);

        gemm_single<<<dim3(8, 16), 128>>>(catp, Wc + (size_t)l * CATD * DMODEL,
                                          bc + (size_t)l * DMODEL, t2p,
                                          NPATCH, DMODEL, CATD, 0);
        add_ln_kernel<<<NPATCH, 256>>>(hp, t2p, ln1_g + l * DMODEL, ln1_b + l * DMODEL);

        gemm_single<<<dim3(32, 16), 128>>>(hp, W1 + (size_t)l * DMODEL * FFD,
                                           b1 + (size_t)l * FFD, ffp,
                                           NPATCH, FFD, DMODEL, 1);
        gemm_single<<<dim3(8, 16), 128>>>(ffp, W2 + (size_t)l * FFD * DMODEL,
                                          b2 + (size_t)l * DMODEL, t2p,
                                          NPATCH, DMODEL, FFD, 0);
        add_ln_kernel<<<NPATCH, 256>>>(hp, t2p, ln2_g + l * DMODEL, ln2_b + l * DMODEL);
    }

    gpool_kernel<<<1, DMODEL>>>(hp, gp);
    head_kernel<<<1, NCLS>>>(gp, head_W, head_b, out);
}

// round 3
// speedup vs baseline: 6.6535x; 1.0677x over previous
#include <cuda_runtime.h>
#include <cstdint>
#include <math.h>

// ---------------- problem constants ----------------
#define NPATCH 500
#define DMODEL 512
#define NHS    5
#define KDIM   32
#define QKVD   160
#define CATD   1536
#define FFD    2048
#define NLAYER 6
#define NBATCH 32
#define NCLS   256
#define LN_EPS 1e-3f
#define RTOT 875     // rows: scale1 [0,500), scale2 [500,750), scale4 [750,875)

#define GBM 64
#define GBN 64
#define GBK 16

// ---------------- scratch ----------------
__device__ float d_h   [NPATCH * DMODEL];
__device__ float d_pool[375 * DMODEL];
__device__ float d_q   [RTOT * QKVD];
__device__ float d_k   [RTOT * QKVD];
__device__ float d_v   [RTOT * QKVD];
__device__ float d_o   [RTOT * QKVD];
__device__ float d_ao  [RTOT * DMODEL];
__device__ float d_cat [NPATCH * CATD];
__device__ float d_ff  [NPATCH * FFD];
__device__ float d_part[4 * NPATCH * DMODEL];
__device__ float d_cs  [DMODEL];
__device__ float d_gv  [DMODEL];

// ---------------- helpers ----------------
__device__ __forceinline__ unsigned long long pack2(float x, float y) {
    unsigned long long r;
    asm("mov.b64 %0, {%1, %2};" : "=l"(r) : "f"(x), "f"(y));
    return r;
}
__device__ __forceinline__ void unpack2(unsigned long long v, float& x, float& y) {
    asm("mov.b64 {%0, %1}, %2;" : "=f"(x), "=f"(y) : "l"(v));
}
__device__ __forceinline__ void fma2(unsigned long long& d, unsigned long long a,
                                     unsigned long long b) {
    asm("fma.rn.f32x2 %0, %1, %2, %0;" : "+l"(d) : "l"(a), "l"(b));
}
__device__ __forceinline__ float gelu_f(float x) {
    return 0.5f * x * (1.f + erff(x * 0.70710678118654752f));
}

// ---------------- core GEMM tile ----------------
// 256 threads. C_tile[64,64] = A[bM:bM+64, kOff:kOff+kLen] @ B[kOff:kOff+kLen, bN:bN+64]
// A row-major with leading dim lda. N % 4 == 0, kLen % 16 == 0.
__device__ __forceinline__ void gemm_core(
    const float* __restrict__ A, const float* __restrict__ B,
    const float* __restrict__ bias, float* __restrict__ C,
    int M, int N, int lda, int kOff, int kLen,
    int bM, int bN, int act, int addBias)
{
    __shared__ float As[2][GBK][68];   // [k][m]
    __shared__ float Bs[2][GBK][GBN];  // [k][n]
    const int tid = threadIdx.x;

    // A LDG: thread -> row ar (0..63), k-quad ac (0,4,8,12)
    const int ar = tid >> 2;
    const int ac = (tid & 3) << 2;
    // B LDG: thread -> k-row br (0..15), col-quad bc (0..60)
    const int br = tid >> 4;
    const int bc = (tid & 15) << 2;

    const int gm = bM + ar;
    const bool aOK = gm < M;
    const float* aSrc = A + (size_t)(aOK ? gm : 0) * lda + kOff + ac;
    const int gn = bN + bc;
    const bool bOK = gn < N;   // gn multiple of 4, N multiple of 4 -> full float4 ok
    const float* bSrc = B + (size_t)(kOff + br) * N + (bOK ? gn : 0);

    const float4 z4 = make_float4(0.f, 0.f, 0.f, 0.f);
    float4 aReg = aOK ? *(const float4*)aSrc : z4;
    float4 bReg = bOK ? *(const float4*)bSrc : z4;

    // prologue STS -> buffer 0
    As[0][ac + 0][ar] = aReg.x;
    As[0][ac + 1][ar] = aReg.y;
    As[0][ac + 2][ar] = aReg.z;
    As[0][ac + 3][ar] = aReg.w;
    *(float4*)&Bs[0][br][bc] = bReg;
    __syncthreads();

    const int T = kLen / GBK;
    const int tm = (tid >> 4) << 2;   // 0..60
    const int tn = (tid & 15) << 2;   // 0..60
    unsigned long long acc[4][2] = {};

    for (int t = 0; t < T; ++t) {
        const int cur = t & 1;
        if (t + 1 < T) {
            aReg = aOK ? *(const float4*)(aSrc + (t + 1) * GBK) : z4;
            bReg = bOK ? *(const float4*)(bSrc + (size_t)(t + 1) * GBK * N) : z4;
        }
        #pragma unroll
        for (int kk = 0; kk < GBK; ++kk) {
            float4 a4 = *(const float4*)&As[cur][kk][tm];
            float4 b4 = *(const float4*)&Bs[cur][kk][tn];
            unsigned long long b01 = pack2(b4.x, b4.y);
            unsigned long long b23 = pack2(b4.z, b4.w);
            unsigned long long aa;
            aa = pack2(a4.x, a4.x); fma2(acc[0][0], aa, b01); fma2(acc[0][1], aa, b23);
            aa = pack2(a4.y, a4.y); fma2(acc[1][0], aa, b01); fma2(acc[1][1], aa, b23);
            aa = pack2(a4.z, a4.z); fma2(acc[2][0], aa, b01); fma2(acc[2][1], aa, b23);
            aa = pack2(a4.w, a4.w); fma2(acc[3][0], aa, b01); fma2(acc[3][1], aa, b23);
        }
        if (t + 1 < T) {
            const int nxt = cur ^ 1;
            As[nxt][ac + 0][ar] = aReg.x;
            As[nxt][ac + 1][ar] = aReg.y;
            As[nxt][ac + 2][ar] = aReg.z;
            As[nxt][ac + 3][ar] = aReg.w;
            *(float4*)&Bs[nxt][br][bc] = bReg;
        }
        __syncthreads();
    }

    const int col = bN + tn;
    if (col < N) {
        float4 bb = addBias ? *(const float4*)(bias + col) : z4;
        #pragma unroll
        for (int i = 0; i < 4; ++i) {
            int row = bM + tm + i;
            if (row >= M) continue;
            float c0, c1, c2, c3;
            unpack2(acc[i][0], c0, c1);
            unpack2(acc[i][1], c2, c3);
            c0 += bb.x; c1 += bb.y; c2 += bb.z; c3 += bb.w;
            if (act) { c0 = gelu_f(c0); c1 = gelu_f(c1); c2 = gelu_f(c2); c3 = gelu_f(c3); }
            *(float4*)(C + (size_t)row * N + col) = make_float4(c0, c1, c2, c3);
        }
    }
}

// ---------------- GEMM wrappers ----------------
__global__ void __launch_bounds__(256) gemm_std(
    const float* __restrict__ A, const float* __restrict__ B,
    const float* __restrict__ bias, float* __restrict__ C,
    int M, int N, int K, int act)
{
    int bM = blockIdx.y * GBM;
    if (bM >= M) return;
    gemm_core(A, B, bias, C, M, N, K, 0, K, bM, blockIdx.x * GBN, act, 1);
}

// split-K: grid.z = split index, chunk of sk columns of K; partials at C + z*M*N
__global__ void __launch_bounds__(256) gemm_splitk(
    const float* __restrict__ A, const float* __restrict__ B,
    float* __restrict__ C, int M, int N, int K, int sk)
{
    int bM = blockIdx.y * GBM;
    if (bM >= M) return;
    int z = blockIdx.z;
    gemm_core(A, B, nullptr, C + (size_t)z * M * N, M, N, K, z * sk, sk,
              bM, blockIdx.x * GBN, 0, 0);
}

__constant__ int c_Ms[3] = {500, 250, 125};
__constant__ int c_ro[3] = {0, 500, 750};

__global__ void __launch_bounds__(256) gemm_qkv(
    const float* __restrict__ h, const float* __restrict__ pool,
    const float* __restrict__ Wq, const float* __restrict__ Wk, const float* __restrict__ Wv,
    const float* __restrict__ bq, const float* __restrict__ bk, const float* __restrict__ bv,
    float* __restrict__ q, float* __restrict__ k, float* __restrict__ v)
{
    int z = blockIdx.z;
    int si = z / 3, which = z - si * 3;
    int M = c_Ms[si];
    int bM = blockIdx.y * GBM;
    if (bM >= M) return;
    const float* A = (si == 0) ? h : (pool + (si == 2 ? 250 * DMODEL : 0));
    const float* W = (which == 0) ? Wq : (which == 1) ? Wk : Wv;
    const float* bb = (which == 0) ? bq : (which == 1) ? bk : bv;
    float* Cb = (which == 0) ? q : (which == 1) ? k : v;
    gemm_core(A, W + (size_t)si * DMODEL * QKVD, bb + (size_t)si * QKVD,
              Cb + (size_t)c_ro[si] * QKVD, M, QKVD, DMODEL, 0, DMODEL,
              bM, blockIdx.x * GBN, 0, 1);
}

__global__ void __launch_bounds__(256) gemm_wo(
    const float* __restrict__ o, const float* __restrict__ Wo,
    const float* __restrict__ bo, float* __restrict__ ao)
{
    int si = blockIdx.z;
    int M = c_Ms[si];
    int bM = blockIdx.y * GBM;
    if (bM >= M) return;
    gemm_core(o + (size_t)c_ro[si] * QKVD, Wo + (size_t)si * QKVD * DMODEL,
              bo + (size_t)si * DMODEL, ao + (size_t)c_ro[si] * DMODEL,
              M, DMODEL, QKVD, 0, QKVD, bM, blockIdx.x * GBN, 0, 1);
}

// ---------------- small kernels ----------------
__global__ void colsum_kernel(const float* __restrict__ W, float* __restrict__ cs) {
    int d = threadIdx.x;
    float s = 0.f;
    #pragma unroll 4
    for (int p = 0; p < 100; p++) s += W[p * DMODEL + d];
    cs[d] = s;
}

__global__ void init_h_kernel(const float* __restrict__ cs, const float* __restrict__ ln_in_b,
                              const float* __restrict__ patch_b, const float* __restrict__ pos,
                              float* __restrict__ h) {
    int n = blockIdx.x, d = threadIdx.x;
    h[n * DMODEL + d] = ln_in_b[0] * cs[d] + patch_b[d] + pos[n * DMODEL + d];
}

__global__ void pool_kernel(const float* __restrict__ h, float* __restrict__ p) {
    int i = blockIdx.x, d = threadIdx.x;
    if (i < 250) {
        p[i * DMODEL + d] = 0.5f * (h[(2 * i) * DMODEL + d] + h[(2 * i + 1) * DMODEL + d]);
    } else {
        int j = i - 250;
        p[i * DMODEL + d] = 0.25f * (h[(4 * j) * DMODEL + d] + h[(4 * j + 1) * DMODEL + d] +
                                     h[(4 * j + 2) * DMODEL + d] + h[(4 * j + 3) * DMODEL + d]);
    }
}

// attention, all scales in one launch; warp per (scale,query,head); 4-way unroll
__global__ void attn_kernel(const float* __restrict__ q, const float* __restrict__ k,
                            const float* __restrict__ v, float* __restrict__ o) {
    int w = blockIdx.x * 8 + (threadIdx.x >> 5);
    int lane = threadIdx.x & 31;
    if (w >= 4375) return;
    int base, Ns, ro;
    if (w < 2500)      { base = 0;    Ns = 500; ro = 0; }
    else if (w < 3750) { base = 2500; Ns = 250; ro = 500; }
    else               { base = 3750; Ns = 125; ro = 750; }
    int local = w - base;
    int n = local / 5, h = local - n * 5;
    const float scale = 0.1767766952966369f;  // 1/sqrt(32)
    float qv = q[(size_t)(ro + n) * QKVD + h * KDIM + lane] * scale;
    const float* kp = k + (size_t)ro * QKVD + h * KDIM + lane;
    const float* vp = v + (size_t)ro * QKVD + h * KDIM + lane;
    float mmax = -INFINITY, ssum = 0.f, oacc = 0.f;
    int m = 0;
    for (; m + 4 <= Ns; m += 4) {
        float s0 = qv * kp[(size_t)(m + 0) * QKVD];
        float s1 = qv * kp[(size_t)(m + 1) * QKVD];
        float s2 = qv * kp[(size_t)(m + 2) * QKVD];
        float s3 = qv * kp[(size_t)(m + 3) * QKVD];
        #pragma unroll
        for (int off = 16; off; off >>= 1) {
            s0 += __shfl_xor_sync(0xffffffffu, s0, off);
            s1 += __shfl_xor_sync(0xffffffffu, s1, off);
            s2 += __shfl_xor_sync(0xffffffffu, s2, off);
            s3 += __shfl_xor_sync(0xffffffffu, s3, off);
        }
        float smax = fmaxf(fmaxf(s0, s1), fmaxf(s2, s3));
        float nm = fmaxf(mmax, smax);
        float corr = __expf(mmax - nm);
        float p0 = __expf(s0 - nm), p1 = __expf(s1 - nm);
        float p2 = __expf(s2 - nm), p3 = __expf(s3 - nm);
        float v0 = vp[(size_t)(m + 0) * QKVD], v1 = vp[(size_t)(m + 1) * QKVD];
        float v2 = vp[(size_t)(m + 2) * QKVD], v3 = vp[(size_t)(m + 3) * QKVD];
        ssum = ssum * corr + ((p0 + p1) + (p2 + p3));
        oacc = oacc * corr + ((p0 * v0 + p1 * v1) + (p2 * v2 + p3 * v3));
        mmax = nm;
    }
    for (; m < Ns; m++) {
        float s = qv * kp[(size_t)m * QKVD];
        #pragma unroll
        for (int off = 16; off; off >>= 1) s += __shfl_xor_sync(0xffffffffu, s, off);
        float nm = fmaxf(mmax, s);
        float corr = __expf(mmax - nm);
        float p = __expf(s - nm);
        ssum = ssum * corr + p;
        oacc = oacc * corr + p * vp[(size_t)m * QKVD];
        mmax = nm;
    }
    o[(size_t)(ro + n) * QKVD + h * KDIM + lane] = oacc / ssum;
}

__global__ void cat_kernel(const float* __restrict__ ao, float* __restrict__ cat) {
    int n = blockIdx.x, d = threadIdx.x;
    cat[n * CATD + d]        = ao[n * DMODEL + d];
    cat[n * CATD + 512 + d]  = ao[(500 + (n >> 1)) * DMODEL + d];
    cat[n * CATD + 1024 + d] = ao[(750 + (n >> 2)) * DMODEL + d];
}

// h[n,:] = LayerNorm(h[n,:] + bias + sum_{s<S} part[s][n,:]) * g + b
__global__ void reduce_add_ln_kernel(const float* __restrict__ part, int S,
                                     const float* __restrict__ bias,
                                     float* __restrict__ h,
                                     const float* __restrict__ g,
                                     const float* __restrict__ b) {
    int n = blockIdx.x, t = threadIdx.x;
    __shared__ float red[8];
    __shared__ float stat;
    float v0 = h[n * DMODEL + t]       + bias[t];
    float v1 = h[n * DMODEL + t + 256] + bias[t + 256];
    for (int s = 0; s < S; s++) {
        v0 += part[(size_t)s * NPATCH * DMODEL + n * DMODEL + t];
        v1 += part[(size_t)s * NPATCH * DMODEL + n * DMODEL + t + 256];
    }

    float s = v0 + v1;
    #pragma unroll
    for (int o = 16; o; o >>= 1) s += __shfl_xor_sync(0xffffffffu, s, o);
    if ((t & 31) == 0) red[t >> 5] = s;
    __syncthreads();
    if (t < 32) {
        float x = (t < 8) ? red[t] : 0.f;
        #pragma unroll
        for (int o = 4; o; o >>= 1) x += __shfl_xor_sync(0xffffffffu, x, o);
        if (t == 0) stat = x / (float)DMODEL;
    }
    __syncthreads();
    float mean = stat;
    float dd0 = v0 - mean, dd1 = v1 - mean;

    __syncthreads();
    float vs = dd0 * dd0 + dd1 * dd1;
    #pragma unroll
    for (int o = 16; o; o >>= 1) vs += __shfl_xor_sync(0xffffffffu, vs, o);
    if ((t & 31) == 0) red[t >> 5] = vs;
    __syncthreads();
    if (t < 32) {
        float x = (t < 8) ? red[t] : 0.f;
        #pragma unroll
        for (int o = 4; o; o >>= 1) x += __shfl_xor_sync(0xffffffffu, x, o);
        if (t == 0) stat = rsqrtf(x / (float)DMODEL + LN_EPS);
    }
    __syncthreads();
    float rstd = stat;
    h[n * DMODEL + t]       = dd0 * rstd * g[t]       + b[t];
    h[n * DMODEL + t + 256] = dd1 * rstd * g[t + 256] + b[t + 256];
}

__global__ void gpool_kernel(const float* __restrict__ h, float* __restrict__ g) {
    int d = threadIdx.x;
    float s = 0.f;
    for (int n = 0; n < NPATCH; n++) s += h[n * DMODEL + d];
    g[d] = s / (float)NPATCH;
}

__global__ void head_kernel(const float* __restrict__ g, const float* __restrict__ W,
                            const float* __restrict__ b, float* __restrict__ out) {
    __shared__ float gs[DMODEL];
    __shared__ float red[8];
    __shared__ float stat;
    int t = threadIdx.x;
    gs[t] = g[t]; gs[t + 256] = g[t + 256];
    __syncthreads();
    float acc = b[t];
    #pragma unroll 4
    for (int d = 0; d < DMODEL; d++) acc += gs[d] * W[d * NCLS + t];

    float m = acc;
    #pragma unroll
    for (int o = 16; o; o >>= 1) m = fmaxf(m, __shfl_xor_sync(0xffffffffu, m, o));
    if ((t & 31) == 0) red[t >> 5] = m;
    __syncthreads();
    if (t < 32) {
        float x = (t < 8) ? red[t] : -INFINITY;
        #pragma unroll
        for (int o = 4; o; o >>= 1) x = fmaxf(x, __shfl_xor_sync(0xffffffffu, x, o));
        if (t == 0) stat = x;
    }
    __syncthreads();
    float e = expf(acc - stat);
    __syncthreads();
    float s = e;
    #pragma unroll
    for (int o = 16; o; o >>= 1) s += __shfl_xor_sync(0xffffffffu, s, o);
    if ((t & 31) == 0) red[t >> 5] = s;
    __syncthreads();
    if (t < 32) {
        float x = (t < 8) ? red[t] : 0.f;
        #pragma unroll
        for (int o = 4; o; o >>= 1) x += __shfl_xor_sync(0xffffffffu, x, o);
        if (t == 0) stat = x;
    }
    __syncthreads();
    float p = e / stat;
    for (int bb = 0; bb < NBATCH; bb++) out[bb * NCLS + t] = p;
}

// ---------------- host launcher ----------------
extern "C" void kernel_launch(void* const* d_in, const int* in_sizes, int n_in,
                              void* d_out, int out_size) {
    const float* ln_in_b = (const float*)d_in[2];
    const float* patch_W = (const float*)d_in[3];
    const float* patch_b = (const float*)d_in[4];
    const float* pos_emb = (const float*)d_in[5];
    const float* Wq = (const float*)d_in[6];
    const float* bq = (const float*)d_in[7];
    const float* Wk = (const float*)d_in[8];
    const float* bk = (const float*)d_in[9];
    const float* Wv = (const float*)d_in[10];
    const float* bv = (const float*)d_in[11];
    const float* Wo = (const float*)d_in[12];
    const float* bo = (const float*)d_in[13];
    const float* Wc = (const float*)d_in[14];
    const float* bc = (const float*)d_in[15];
    const float* ln1_g = (const float*)d_in[16];
    const float* ln1_b = (const float*)d_in[17];
    const float* W1 = (const float*)d_in[18];
    const float* b1 = (const float*)d_in[19];
    const float* W2 = (const float*)d_in[20];
    const float* b2 = (const float*)d_in[21];
    const float* ln2_g = (const float*)d_in[22];
    const float* ln2_b = (const float*)d_in[23];
    const float* head_W = (const float*)d_in[24];
    const float* head_b = (const float*)d_in[25];
    float* out = (float*)d_out;

    float *hp, *pp, *qp, *kp, *vp, *op, *aop, *catp, *ffp, *partp, *csp, *gp;
    cudaGetSymbolAddress((void**)&hp,  d_h);
    cudaGetSymbolAddress((void**)&pp,  d_pool);
    cudaGetSymbolAddress((void**)&qp,  d_q);
    cudaGetSymbolAddress((void**)&kp,  d_k);
    cudaGetSymbolAddress((void**)&vp,  d_v);
    cudaGetSymbolAddress((void**)&op,  d_o);
    cudaGetSymbolAddress((void**)&aop, d_ao);
    cudaGetSymbolAddress((void**)&catp, d_cat);
    cudaGetSymbolAddress((void**)&ffp, d_ff);
    cudaGetSymbolAddress((void**)&partp, d_part);
    cudaGetSymbolAddress((void**)&csp, d_cs);
    cudaGetSymbolAddress((void**)&gp,  d_gv);

    colsum_kernel<<<1, DMODEL>>>(patch_W, csp);
    init_h_kernel<<<NPATCH, DMODEL>>>(csp, ln_in_b, patch_b, pos_emb, hp);

    for (int l = 0; l < NLAYER; l++) {
        size_t wqkv = (size_t)l * 3 * DMODEL * QKVD;
        size_t bqkv = (size_t)l * 3 * QKVD;
        size_t wwo  = (size_t)l * 3 * QKVD * DMODEL;
        size_t bwo  = (size_t)l * 3 * DMODEL;

        pool_kernel<<<375, DMODEL>>>(hp, pp);
        gemm_qkv<<<dim3(3, 8, 9), 256>>>(hp, pp,
            Wq + wqkv, Wk + wqkv, Wv + wqkv, bq + bqkv, bk + bqkv, bv + bqkv,
            qp, kp, vp);
        attn_kernel<<<547, 256>>>(qp, kp, vp, op);
        gemm_wo<<<dim3(8, 8, 3), 256>>>(op, Wo + wwo, bo + bwo, aop);
        cat_kernel<<<NPATCH, DMODEL>>>(aop, catp);

        // combine: split-K 3x512 -> partials -> fused reduce+bias+residual+LN
        gemm_splitk<<<dim3(8, 8, 3), 256>>>(catp, Wc + (size_t)l * CATD * DMODEL,
                                            partp, NPATCH, DMODEL, CATD, 512);
        reduce_add_ln_kernel<<<NPATCH, 256>>>(partp, 3, bc + (size_t)l * DMODEL, hp,
                                              ln1_g + l * DMODEL, ln1_b + l * DMODEL);

        // FFN
        gemm_std<<<dim3(32, 8), 256>>>(hp, W1 + (size_t)l * DMODEL * FFD,
                                       b1 + (size_t)l * FFD, ffp,
                                       NPATCH, FFD, DMODEL, 1);
        gemm_splitk<<<dim3(8, 8, 4), 256>>>(ffp, W2 + (size_t)l * FFD * DMODEL,
                                            partp, NPATCH, DMODEL, FFD, 512);
        reduce_add_ln_kernel<<<NPATCH, 256>>>(partp, 4, b2 + (size_t)l * DMODEL, hp,
                                              ln2_g + l * DMODEL, ln2_b + l * DMODEL);
    }

    gpool_kernel<<<1, DMODEL>>>(hp, gp);
    head_kernel<<<1, NCLS>>>(gp, head_W, head_b, out);
}

// round 4
// speedup vs baseline: 8.4086x; 1.2638x over previous
#include <cuda_runtime.h>
#include <cstdint>
#include <math.h>

// ---------------- problem constants ----------------
#define NPATCH 500
#define DMODEL 512
#define NHS    5
#define KDIM   32
#define QKVD   160
#define CATD   1536
#define FFD    2048
#define NLAYER 6
#define NBATCH 32
#define NCLS   256
#define LN_EPS 1e-3f
#define RTOT 875     // rows: scale1 [0,500), scale2 [500,750), scale4 [750,875)

#define GBM 64
#define GBN 64
#define GBK 16

// ---------------- scratch ----------------
__device__ float d_h   [NPATCH * DMODEL];
__device__ float d_pool[375 * DMODEL];
__device__ float d_q   [RTOT * QKVD];
__device__ float d_k   [RTOT * QKVD];
__device__ float d_v   [RTOT * QKVD];
__device__ float d_o   [RTOT * QKVD];
__device__ float d_ao  [RTOT * DMODEL];
__device__ float d_cat [NPATCH * CATD];
__device__ float d_ff  [NPATCH * FFD];
__device__ float d_part[4 * NPATCH * DMODEL];
__device__ float d_cs  [DMODEL];
__device__ float d_gv  [DMODEL];

// ---------------- helpers ----------------
__device__ __forceinline__ uint32_t f2tf(float f) {
    uint32_t u;
    asm("cvt.rna.tf32.f32 %0, %1;" : "=r"(u) : "f"(f));
    return u;
}
__device__ __forceinline__ void mma_tf32(float* c, const uint32_t* a, const uint32_t* b) {
    asm volatile(
        "mma.sync.aligned.m16n8k8.row.col.f32.tf32.tf32.f32 "
        "{%0,%1,%2,%3}, {%4,%5,%6,%7}, {%8,%9}, {%0,%1,%2,%3};"
        : "+f"(c[0]), "+f"(c[1]), "+f"(c[2]), "+f"(c[3])
        : "r"(a[0]), "r"(a[1]), "r"(a[2]), "r"(a[3]), "r"(b[0]), "r"(b[1]));
}
__device__ __forceinline__ float gelu_f(float x) {
    return 0.5f * x * (1.f + erff(x * 0.70710678118654752f));
}

// ---------------- core GEMM tile (tf32 tensor-core) ----------------
// 128 threads, block tile 64x64, BK=16. C = A[M,K]@B[K,N] (+bias)(+gelu).
// A row-major (lda), B row-major (N). kLen % 16 == 0, N % 4 == 0.
__device__ __forceinline__ void gemm_core(
    const float* __restrict__ A, const float* __restrict__ B,
    const float* __restrict__ bias, float* __restrict__ C,
    int M, int N, int lda, int kOff, int kLen,
    int bM, int bN, int act, int addBias)
{
    __shared__ uint32_t As[2][64][20];   // [m][k] pad 20
    __shared__ uint32_t Bs[2][16][72];   // [k][n] pad 8

    const int tid  = threadIdx.x;
    const int lane = tid & 31;
    const int warp = tid >> 5;
    const int wm = (warp & 1) << 5;      // warp m-offset in tile
    const int wn = (warp >> 1) << 5;     // warp n-offset in tile
    const int g = lane >> 2;             // 0..7
    const int t = lane & 3;              // 0..3

    // global->smem mapping: A: rows ar, ar+32 ; k-quad akq
    const int ar  = tid >> 2;            // 0..31
    const int akq = (tid & 3) << 2;      // 0,4,8,12
    const int m1 = min(bM + ar, M - 1);
    const int m2 = min(bM + ar + 32, M - 1);
    const float* aSrc1 = A + (size_t)m1 * lda + kOff + akq;
    const float* aSrc2 = A + (size_t)m2 * lda + kOff + akq;

    // B: k-rows bk, bk+8 ; n-quad bnq
    const int bk  = tid >> 4;            // 0..7
    const int bnq = (tid & 15) << 2;     // 0..60
    const bool bOK = (bN + bnq) < N;
    const float* bSrc1 = B + (size_t)(kOff + bk) * N + bN + (bOK ? bnq : 0);
    const float* bSrc2 = B + (size_t)(kOff + bk + 8) * N + bN + (bOK ? bnq : 0);

    const float4 z4 = make_float4(0.f, 0.f, 0.f, 0.f);
    float4 a1R = *(const float4*)aSrc1;
    float4 a2R = *(const float4*)aSrc2;
    float4 b1R = bOK ? *(const float4*)bSrc1 : z4;
    float4 b2R = bOK ? *(const float4*)bSrc2 : z4;

    // prologue STS -> buffer 0
    {
        uint4 u;
        u.x = f2tf(a1R.x); u.y = f2tf(a1R.y); u.z = f2tf(a1R.z); u.w = f2tf(a1R.w);
        *(uint4*)&As[0][ar][akq] = u;
        u.x = f2tf(a2R.x); u.y = f2tf(a2R.y); u.z = f2tf(a2R.z); u.w = f2tf(a2R.w);
        *(uint4*)&As[0][ar + 32][akq] = u;
        u.x = f2tf(b1R.x); u.y = f2tf(b1R.y); u.z = f2tf(b1R.z); u.w = f2tf(b1R.w);
        *(uint4*)&Bs[0][bk][bnq] = u;
        u.x = f2tf(b2R.x); u.y = f2tf(b2R.y); u.z = f2tf(b2R.z); u.w = f2tf(b2R.w);
        *(uint4*)&Bs[0][bk + 8][bnq] = u;
    }
    __syncthreads();

    float acc[2][4][4] = {};
    const int T = kLen >> 4;

    for (int tt = 0; tt < T; ++tt) {
        const int cur = tt & 1;
        if (tt + 1 < T) {
            const int ko = (tt + 1) << 4;
            a1R = *(const float4*)(aSrc1 + ko);
            a2R = *(const float4*)(aSrc2 + ko);
            b1R = bOK ? *(const float4*)(bSrc1 + (size_t)ko * N) : z4;
            b2R = bOK ? *(const float4*)(bSrc2 + (size_t)ko * N) : z4;
        }
        #pragma unroll
        for (int ks = 0; ks < 2; ++ks) {
            const int k0 = ks << 3;
            uint32_t af[2][4];
            #pragma unroll
            for (int i = 0; i < 2; ++i) {
                const int r = wm + (i << 4) + g;
                af[i][0] = As[cur][r][k0 + t];
                af[i][1] = As[cur][r + 8][k0 + t];
                af[i][2] = As[cur][r][k0 + t + 4];
                af[i][3] = As[cur][r + 8][k0 + t + 4];
            }
            uint32_t bf[4][2];
            #pragma unroll
            for (int j = 0; j < 4; ++j) {
                const int c = wn + (j << 3) + g;
                bf[j][0] = Bs[cur][k0 + t][c];
                bf[j][1] = Bs[cur][k0 + t + 4][c];
            }
            #pragma unroll
            for (int i = 0; i < 2; ++i)
                #pragma unroll
                for (int j = 0; j < 4; ++j)
                    mma_tf32(acc[i][j], af[i], bf[j]);
        }
        if (tt + 1 < T) {
            const int nxt = cur ^ 1;
            uint4 u;
            u.x = f2tf(a1R.x); u.y = f2tf(a1R.y); u.z = f2tf(a1R.z); u.w = f2tf(a1R.w);
            *(uint4*)&As[nxt][ar][akq] = u;
            u.x = f2tf(a2R.x); u.y = f2tf(a2R.y); u.z = f2tf(a2R.z); u.w = f2tf(a2R.w);
            *(uint4*)&As[nxt][ar + 32][akq] = u;
            u.x = f2tf(b1R.x); u.y = f2tf(b1R.y); u.z = f2tf(b1R.z); u.w = f2tf(b1R.w);
            *(uint4*)&Bs[nxt][bk][bnq] = u;
            u.x = f2tf(b2R.x); u.y = f2tf(b2R.y); u.z = f2tf(b2R.z); u.w = f2tf(b2R.w);
            *(uint4*)&Bs[nxt][bk + 8][bnq] = u;
            __syncthreads();
        }
    }

    // epilogue
    #pragma unroll
    for (int i = 0; i < 2; ++i) {
        const int r0 = bM + wm + (i << 4) + g;
        const int r1 = r0 + 8;
        #pragma unroll
        for (int j = 0; j < 4; ++j) {
            const int col = bN + wn + (j << 3) + (t << 1);
            if (col >= N) continue;
            float b0v = 0.f, b1v = 0.f;
            if (addBias) {
                float2 bb = *(const float2*)(bias + col);
                b0v = bb.x; b1v = bb.y;
            }
            float c0 = acc[i][j][0] + b0v, c1 = acc[i][j][1] + b1v;
            float c2 = acc[i][j][2] + b0v, c3 = acc[i][j][3] + b1v;
            if (act) { c0 = gelu_f(c0); c1 = gelu_f(c1); c2 = gelu_f(c2); c3 = gelu_f(c3); }
            if (r0 < M) *(float2*)(C + (size_t)r0 * N + col) = make_float2(c0, c1);
            if (r1 < M) *(float2*)(C + (size_t)r1 * N + col) = make_float2(c2, c3);
        }
    }
}

// ---------------- GEMM wrappers ----------------
__global__ void __launch_bounds__(128) gemm_std(
    const float* __restrict__ A, const float* __restrict__ B,
    const float* __restrict__ bias, float* __restrict__ C,
    int M, int N, int K, int act)
{
    int bM = blockIdx.y * GBM;
    if (bM >= M) return;
    gemm_core(A, B, bias, C, M, N, K, 0, K, bM, blockIdx.x * GBN, act, 1);
}

// split-K: grid.z = split index, chunk of sk columns of K; partials at C + z*M*N
__global__ void __launch_bounds__(128) gemm_splitk(
    const float* __restrict__ A, const float* __restrict__ B,
    float* __restrict__ C, int M, int N, int K, int sk)
{
    int bM = blockIdx.y * GBM;
    if (bM >= M) return;
    int z = blockIdx.z;
    gemm_core(A, B, nullptr, C + (size_t)z * M * N, M, N, K, z * sk, sk,
              bM, blockIdx.x * GBN, 0, 0);
}

__constant__ int c_Ms[3] = {500, 250, 125};
__constant__ int c_ro[3] = {0, 500, 750};

__global__ void __launch_bounds__(128) gemm_qkv(
    const float* __restrict__ h, const float* __restrict__ pool,
    const float* __restrict__ Wq, const float* __restrict__ Wk, const float* __restrict__ Wv,
    const float* __restrict__ bq, const float* __restrict__ bk, const float* __restrict__ bv,
    float* __restrict__ q, float* __restrict__ k, float* __restrict__ v)
{
    int z = blockIdx.z;
    int si = z / 3, which = z - si * 3;
    int M = c_Ms[si];
    int bM = blockIdx.y * GBM;
    if (bM >= M) return;
    const float* A = (si == 0) ? h : (pool + (si == 2 ? 250 * DMODEL : 0));
    const float* W = (which == 0) ? Wq : (which == 1) ? Wk : Wv;
    const float* bb = (which == 0) ? bq : (which == 1) ? bk : bv;
    float* Cb = (which == 0) ? q : (which == 1) ? k : v;
    gemm_core(A, W + (size_t)si * DMODEL * QKVD, bb + (size_t)si * QKVD,
              Cb + (size_t)c_ro[si] * QKVD, M, QKVD, DMODEL, 0, DMODEL,
              bM, blockIdx.x * GBN, 0, 1);
}

__global__ void __launch_bounds__(128) gemm_wo(
    const float* __restrict__ o, const float* __restrict__ Wo,
    const float* __restrict__ bo, float* __restrict__ ao)
{
    int si = blockIdx.z;
    int M = c_Ms[si];
    int bM = blockIdx.y * GBM;
    if (bM >= M) return;
    gemm_core(o + (size_t)c_ro[si] * QKVD, Wo + (size_t)si * QKVD * DMODEL,
              bo + (size_t)si * DMODEL, ao + (size_t)c_ro[si] * DMODEL,
              M, DMODEL, QKVD, 0, QKVD, bM, blockIdx.x * GBN, 0, 1);
}

// ---------------- small kernels ----------------
__global__ void colsum_kernel(const float* __restrict__ W, float* __restrict__ cs) {
    int d = threadIdx.x;
    float s = 0.f;
    #pragma unroll 4
    for (int p = 0; p < 100; p++) s += W[p * DMODEL + d];
    cs[d] = s;
}

__global__ void init_h_kernel(const float* __restrict__ cs, const float* __restrict__ ln_in_b,
                              const float* __restrict__ patch_b, const float* __restrict__ pos,
                              float* __restrict__ h) {
    int n = blockIdx.x, d = threadIdx.x;
    h[n * DMODEL + d] = ln_in_b[0] * cs[d] + patch_b[d] + pos[n * DMODEL + d];
}

__global__ void pool_kernel(const float* __restrict__ h, float* __restrict__ p) {
    int i = blockIdx.x, d = threadIdx.x;
    if (i < 250) {
        p[i * DMODEL + d] = 0.5f * (h[(2 * i) * DMODEL + d] + h[(2 * i + 1) * DMODEL + d]);
    } else {
        int j = i - 250;
        p[i * DMODEL + d] = 0.25f * (h[(4 * j) * DMODEL + d] + h[(4 * j + 1) * DMODEL + d] +
                                     h[(4 * j + 2) * DMODEL + d] + h[(4 * j + 3) * DMODEL + d]);
    }
}

// attention, all scales in one launch; warp per (scale,query,head); 4-way unroll
__global__ void attn_kernel(const float* __restrict__ q, const float* __restrict__ k,
                            const float* __restrict__ v, float* __restrict__ o) {
    int w = blockIdx.x * 8 + (threadIdx.x >> 5);
    int lane = threadIdx.x & 31;
    if (w >= 4375) return;
    int base, Ns, ro;
    if (w < 2500)      { base = 0;    Ns = 500; ro = 0; }
    else if (w < 3750) { base = 2500; Ns = 250; ro = 500; }
    else               { base = 3750; Ns = 125; ro = 750; }
    int local = w - base;
    int n = local / 5, h = local - n * 5;
    const float scale = 0.1767766952966369f;  // 1/sqrt(32)
    float qv = q[(size_t)(ro + n) * QKVD + h * KDIM + lane] * scale;
    const float* kp = k + (size_t)ro * QKVD + h * KDIM + lane;
    const float* vp = v + (size_t)ro * QKVD + h * KDIM + lane;
    float mmax = -INFINITY, ssum = 0.f, oacc = 0.f;
    int m = 0;
    for (; m + 4 <= Ns; m += 4) {
        float s0 = qv * kp[(size_t)(m + 0) * QKVD];
        float s1 = qv * kp[(size_t)(m + 1) * QKVD];
        float s2 = qv * kp[(size_t)(m + 2) * QKVD];
        float s3 = qv * kp[(size_t)(m + 3) * QKVD];
        #pragma unroll
        for (int off = 16; off; off >>= 1) {
            s0 += __shfl_xor_sync(0xffffffffu, s0, off);
            s1 += __shfl_xor_sync(0xffffffffu, s1, off);
            s2 += __shfl_xor_sync(0xffffffffu, s2, off);
            s3 += __shfl_xor_sync(0xffffffffu, s3, off);
        }
        float smax = fmaxf(fmaxf(s0, s1), fmaxf(s2, s3));
        float nm = fmaxf(mmax, smax);
        float corr = __expf(mmax - nm);
        float p0 = __expf(s0 - nm), p1 = __expf(s1 - nm);
        float p2 = __expf(s2 - nm), p3 = __expf(s3 - nm);
        float v0 = vp[(size_t)(m + 0) * QKVD], v1 = vp[(size_t)(m + 1) * QKVD];
        float v2 = vp[(size_t)(m + 2) * QKVD], v3 = vp[(size_t)(m + 3) * QKVD];
        ssum = ssum * corr + ((p0 + p1) + (p2 + p3));
        oacc = oacc * corr + ((p0 * v0 + p1 * v1) + (p2 * v2 + p3 * v3));
        mmax = nm;
    }
    for (; m < Ns; m++) {
        float s = qv * kp[(size_t)m * QKVD];
        #pragma unroll
        for (int off = 16; off; off >>= 1) s += __shfl_xor_sync(0xffffffffu, s, off);
        float nm = fmaxf(mmax, s);
        float corr = __expf(mmax - nm);
        float p = __expf(s - nm);
        ssum = ssum * corr + p;
        oacc = oacc * corr + p * vp[(size_t)m * QKVD];
        mmax = nm;
    }
    o[(size_t)(ro + n) * QKVD + h * KDIM + lane] = oacc / ssum;
}

__global__ void cat_kernel(const float* __restrict__ ao, float* __restrict__ cat) {
    int n = blockIdx.x, d = threadIdx.x;
    cat[n * CATD + d]        = ao[n * DMODEL + d];
    cat[n * CATD + 512 + d]  = ao[(500 + (n >> 1)) * DMODEL + d];
    cat[n * CATD + 1024 + d] = ao[(750 + (n >> 2)) * DMODEL + d];
}

// h[n,:] = LayerNorm(h[n,:] + bias + sum_{s<S} part[s][n,:]) * g + b
__global__ void reduce_add_ln_kernel(const float* __restrict__ part, int S,
                                     const float* __restrict__ bias,
                                     float* __restrict__ h,
                                     const float* __restrict__ g,
                                     const float* __restrict__ b) {
    int n = blockIdx.x, t = threadIdx.x;
    __shared__ float red[8];
    __shared__ float stat;
    float v0 = h[n * DMODEL + t]       + bias[t];
    float v1 = h[n * DMODEL + t + 256] + bias[t + 256];
    for (int s = 0; s < S; s++) {
        v0 += part[(size_t)s * NPATCH * DMODEL + n * DMODEL + t];
        v1 += part[(size_t)s * NPATCH * DMODEL + n * DMODEL + t + 256];
    }

    float s = v0 + v1;
    #pragma unroll
    for (int o = 16; o; o >>= 1) s += __shfl_xor_sync(0xffffffffu, s, o);
    if ((t & 31) == 0) red[t >> 5] = s;
    __syncthreads();
    if (t < 32) {
        float x = (t < 8) ? red[t] : 0.f;
        #pragma unroll
        for (int o = 4; o; o >>= 1) x += __shfl_xor_sync(0xffffffffu, x, o);
        if (t == 0) stat = x / (float)DMODEL;
    }
    __syncthreads();
    float mean = stat;
    float dd0 = v0 - mean, dd1 = v1 - mean;

    __syncthreads();
    float vs = dd0 * dd0 + dd1 * dd1;
    #pragma unroll
    for (int o = 16; o; o >>= 1) vs += __shfl_xor_sync(0xffffffffu, vs, o);
    if ((t & 31) == 0) red[t >> 5] = vs;
    __syncthreads();
    if (t < 32) {
        float x = (t < 8) ? red[t] : 0.f;
        #pragma unroll
        for (int o = 4; o; o >>= 1) x += __shfl_xor_sync(0xffffffffu, x, o);
        if (t == 0) stat = rsqrtf(x / (float)DMODEL + LN_EPS);
    }
    __syncthreads();
    float rstd = stat;
    h[n * DMODEL + t]       = dd0 * rstd * g[t]       + b[t];
    h[n * DMODEL + t + 256] = dd1 * rstd * g[t + 256] + b[t + 256];
}

__global__ void gpool_kernel(const float* __restrict__ h, float* __restrict__ g) {
    int d = threadIdx.x;
    float s = 0.f;
    for (int n = 0; n < NPATCH; n++) s += h[n * DMODEL + d];
    g[d] = s / (float)NPATCH;
}

__global__ void head_kernel(const float* __restrict__ g, const float* __restrict__ W,
                            const float* __restrict__ b, float* __restrict__ out) {
    __shared__ float gs[DMODEL];
    __shared__ float red[8];
    __shared__ float stat;
    int t = threadIdx.x;
    gs[t] = g[t]; gs[t + 256] = g[t + 256];
    __syncthreads();
    float acc = b[t];
    #pragma unroll 4
    for (int d = 0; d < DMODEL; d++) acc += gs[d] * W[d * NCLS + t];

    float m = acc;
    #pragma unroll
    for (int o = 16; o; o >>= 1) m = fmaxf(m, __shfl_xor_sync(0xffffffffu, m, o));
    if ((t & 31) == 0) red[t >> 5] = m;
    __syncthreads();
    if (t < 32) {
        float x = (t < 8) ? red[t] : -INFINITY;
        #pragma unroll
        for (int o = 4; o; o >>= 1) x = fmaxf(x, __shfl_xor_sync(0xffffffffu, x, o));
        if (t == 0) stat = x;
    }
    __syncthreads();
    float e = expf(acc - stat);
    __syncthreads();
    float s = e;
    #pragma unroll
    for (int o = 16; o; o >>= 1) s += __shfl_xor_sync(0xffffffffu, s, o);
    if ((t & 31) == 0) red[t >> 5] = s;
    __syncthreads();
    if (t < 32) {
        float x = (t < 8) ? red[t] : 0.f;
        #pragma unroll
        for (int o = 4; o; o >>= 1) x += __shfl_xor_sync(0xffffffffu, x, o);
        if (t == 0) stat = x;
    }
    __syncthreads();
    float p = e / stat;
    for (int bb = 0; bb < NBATCH; bb++) out[bb * NCLS + t] = p;
}

// ---------------- host launcher ----------------
extern "C" void kernel_launch(void* const* d_in, const int* in_sizes, int n_in,
                              void* d_out, int out_size) {
    const float* ln_in_b = (const float*)d_in[2];
    const float* patch_W = (const float*)d_in[3];
    const float* patch_b = (const float*)d_in[4];
    const float* pos_emb = (const float*)d_in[5];
    const float* Wq = (const float*)d_in[6];
    const float* bq = (const float*)d_in[7];
    const float* Wk = (const float*)d_in[8];
    const float* bk = (const float*)d_in[9];
    const float* Wv = (const float*)d_in[10];
    const float* bv = (const float*)d_in[11];
    const float* Wo = (const float*)d_in[12];
    const float* bo = (const float*)d_in[13];
    const float* Wc = (const float*)d_in[14];
    const float* bc = (const float*)d_in[15];
    const float* ln1_g = (const float*)d_in[16];
    const float* ln1_b = (const float*)d_in[17];
    const float* W1 = (const float*)d_in[18];
    const float* b1 = (const float*)d_in[19];
    const float* W2 = (const float*)d_in[20];
    const float* b2 = (const float*)d_in[21];
    const float* ln2_g = (const float*)d_in[22];
    const float* ln2_b = (const float*)d_in[23];
    const float* head_W = (const float*)d_in[24];
    const float* head_b = (const float*)d_in[25];
    float* out = (float*)d_out;

    float *hp, *pp, *qp, *kp, *vp, *op, *aop, *catp, *ffp, *partp, *csp, *gp;
    cudaGetSymbolAddress((void**)&hp,  d_h);
    cudaGetSymbolAddress((void**)&pp,  d_pool);
    cudaGetSymbolAddress((void**)&qp,  d_q);
    cudaGetSymbolAddress((void**)&kp,  d_k);
    cudaGetSymbolAddress((void**)&vp,  d_v);
    cudaGetSymbolAddress((void**)&op,  d_o);
    cudaGetSymbolAddress((void**)&aop, d_ao);
    cudaGetSymbolAddress((void**)&catp, d_cat);
    cudaGetSymbolAddress((void**)&ffp, d_ff);
    cudaGetSymbolAddress((void**)&partp, d_part);
    cudaGetSymbolAddress((void**)&csp, d_cs);
    cudaGetSymbolAddress((void**)&gp,  d_gv);

    colsum_kernel<<<1, DMODEL>>>(patch_W, csp);
    init_h_kernel<<<NPATCH, DMODEL>>>(csp, ln_in_b, patch_b, pos_emb, hp);

    for (int l = 0; l < NLAYER; l++) {
        size_t wqkv = (size_t)l * 3 * DMODEL * QKVD;
        size_t bqkv = (size_t)l * 3 * QKVD;
        size_t wwo  = (size_t)l * 3 * QKVD * DMODEL;
        size_t bwo  = (size_t)l * 3 * DMODEL;

        pool_kernel<<<375, DMODEL>>>(hp, pp);
        gemm_qkv<<<dim3(3, 8, 9), 128>>>(hp, pp,
            Wq + wqkv, Wk + wqkv, Wv + wqkv, bq + bqkv, bk + bqkv, bv + bqkv,
            qp, kp, vp);
        attn_kernel<<<547, 256>>>(qp, kp, vp, op);
        gemm_wo<<<dim3(8, 8, 3), 128>>>(op, Wo + wwo, bo + bwo, aop);
        cat_kernel<<<NPATCH, DMODEL>>>(aop, catp);

        // combine: split-K 3x512 -> partials -> fused reduce+bias+residual+LN
        gemm_splitk<<<dim3(8, 8, 3), 128>>>(catp, Wc + (size_t)l * CATD * DMODEL,
                                            partp, NPATCH, DMODEL, CATD, 512);
        reduce_add_ln_kernel<<<NPATCH, 256>>>(partp, 3, bc + (size_t)l * DMODEL, hp,
                                              ln1_g + l * DMODEL, ln1_b + l * DMODEL);

        // FFN
        gemm_std<<<dim3(32, 8), 128>>>(hp, W1 + (size_t)l * DMODEL * FFD,
                                       b1 + (size_t)l * FFD, ffp,
                                       NPATCH, FFD, DMODEL, 1);
        gemm_splitk<<<dim3(8, 8, 4), 128>>>(ffp, W2 + (size_t)l * FFD * DMODEL,
                                            partp, NPATCH, DMODEL, FFD, 512);
        reduce_add_ln_kernel<<<NPATCH, 256>>>(partp, 4, b2 + (size_t)l * DMODEL, hp,
                                              ln2_g + l * DMODEL, ln2_b + l * DMODEL);
    }

    gpool_kernel<<<1, DMODEL>>>(hp, gp);
    head_kernel<<<1, NCLS>>>(gp, head_W, head_b, out);
}

// round 5
// speedup vs baseline: 11.9574x; 1.4220x over previous
#include <cuda_runtime.h>
#include <cstdint>
#include <math.h>

// ---------------- problem constants ----------------
#define NPATCH 500
#define DMODEL 512
#define NHS    5
#define KDIM   32
#define QKVD   160
#define CATD   1536
#define FFD    2048
#define NLAYER 6
#define NBATCH 32
#define NCLS   256
#define LN_EPS 1e-3f
#define RTOT 875     // rows: scale1 [0,500), scale2 [500,750), scale4 [750,875)

#define GBM 128
#define GBN 64

// ---------------- scratch ----------------
__device__ float d_h   [NPATCH * DMODEL];
__device__ float d_pool[375 * DMODEL];
__device__ float d_q   [RTOT * QKVD];
__device__ float d_k   [RTOT * QKVD];
__device__ float d_v   [RTOT * QKVD];
__device__ float d_o   [RTOT * QKVD];
__device__ float d_ao  [RTOT * DMODEL];
__device__ float d_cat [NPATCH * CATD];
__device__ float d_ff  [NPATCH * FFD];
__device__ float d_part[6 * NPATCH * DMODEL];
__device__ float d_cs  [DMODEL];
__device__ float d_gv  [DMODEL];

// ---------------- helpers ----------------
__device__ __forceinline__ uint32_t f2tf(float f) {
    uint32_t u;
    asm("cvt.rna.tf32.f32 %0, %1;" : "=r"(u) : "f"(f));
    return u;
}
__device__ __forceinline__ void mma_tf32(float* c, const uint32_t* a, const uint32_t* b) {
    asm volatile(
        "mma.sync.aligned.m16n8k8.row.col.f32.tf32.tf32.f32 "
        "{%0,%1,%2,%3}, {%4,%5,%6,%7}, {%8,%9}, {%0,%1,%2,%3};"
        : "+f"(c[0]), "+f"(c[1]), "+f"(c[2]), "+f"(c[3])
        : "r"(a[0]), "r"(a[1]), "r"(a[2]), "r"(a[3]), "r"(b[0]), "r"(b[1]));
}
__device__ __forceinline__ float gelu_f(float x) {
    return 0.5f * x * (1.f + erff(x * 0.70710678118654752f));
}

// ---------------- core GEMM tile (tf32 tensor-core, 256 thr, 128x64) ----------------
// 8 warps (4x2). Warp tile 32x32 (2 m-subtiles x 4 n-subtiles of m16n8k8).
// A row-major (lda), B row-major (N). kLen % 16 == 0, N % 4 == 0.
__device__ __forceinline__ void gemm_core(
    const float* __restrict__ A, const float* __restrict__ B,
    const float* __restrict__ bias, float* __restrict__ C,
    int M, int N, int lda, int kOff, int kLen,
    int bM, int bN, int act, int addBias)
{
    __shared__ uint32_t As[2][GBM][20];   // [m][k] pad 20 (conflict-free frags)
    __shared__ uint32_t Bs[2][16][72];    // [k][n] pad 8

    const int tid  = threadIdx.x;
    const int lane = tid & 31;
    const int warp = tid >> 5;
    const int wm = (warp & 3) << 5;       // 0,32,64,96
    const int wn = (warp >> 2) << 5;      // 0,32
    const int g = lane >> 2;              // 0..7
    const int t = lane & 3;               // 0..3

    // A: rows ar, ar+64 ; k-quad akq
    const int ar  = tid >> 2;             // 0..63
    const int akq = (tid & 3) << 2;       // 0,4,8,12
    const int m1 = min(bM + ar, M - 1);
    const int m2 = min(bM + ar + 64, M - 1);
    const float* aSrc1 = A + (size_t)m1 * lda + kOff + akq;
    const float* aSrc2 = A + (size_t)m2 * lda + kOff + akq;

    // B: k-row bk ; n-quad bnq (one float4 per thread)
    const int bk  = tid >> 4;             // 0..15
    const int bnq = (tid & 15) << 2;      // 0..60
    const bool bOK = (bN + bnq) < N;
    const float* bSrc = B + (size_t)(kOff + bk) * N + bN + (bOK ? bnq : 0);

    const float4 z4 = make_float4(0.f, 0.f, 0.f, 0.f);
    float4 a1R = *(const float4*)aSrc1;
    float4 a2R = *(const float4*)aSrc2;
    float4 bR  = bOK ? *(const float4*)bSrc : z4;

    {   // prologue STS -> buffer 0
        uint4 u;
        u.x = f2tf(a1R.x); u.y = f2tf(a1R.y); u.z = f2tf(a1R.z); u.w = f2tf(a1R.w);
        *(uint4*)&As[0][ar][akq] = u;
        u.x = f2tf(a2R.x); u.y = f2tf(a2R.y); u.z = f2tf(a2R.z); u.w = f2tf(a2R.w);
        *(uint4*)&As[0][ar + 64][akq] = u;
        u.x = f2tf(bR.x); u.y = f2tf(bR.y); u.z = f2tf(bR.z); u.w = f2tf(bR.w);
        *(uint4*)&Bs[0][bk][bnq] = u;
    }
    __syncthreads();

    float acc[2][4][4] = {};
    const int T = kLen >> 4;

    for (int tt = 0; tt < T; ++tt) {
        const int cur = tt & 1;
        if (tt + 1 < T) {
            const int ko = (tt + 1) << 4;
            a1R = *(const float4*)(aSrc1 + ko);
            a2R = *(const float4*)(aSrc2 + ko);
            bR  = bOK ? *(const float4*)(bSrc + (size_t)ko * N) : z4;
        }
        #pragma unroll
        for (int ks = 0; ks < 2; ++ks) {
            const int k0 = ks << 3;
            uint32_t af[2][4];
            #pragma unroll
            for (int i = 0; i < 2; ++i) {
                const int r = wm + (i << 4) + g;
                af[i][0] = As[cur][r][k0 + t];
                af[i][1] = As[cur][r + 8][k0 + t];
                af[i][2] = As[cur][r][k0 + t + 4];
                af[i][3] = As[cur][r + 8][k0 + t + 4];
            }
            uint32_t bf[4][2];
            #pragma unroll
            for (int j = 0; j < 4; ++j) {
                const int c = wn + (j << 3) + g;
                bf[j][0] = Bs[cur][k0 + t][c];
                bf[j][1] = Bs[cur][k0 + t + 4][c];
            }
            #pragma unroll
            for (int i = 0; i < 2; ++i)
                #pragma unroll
                for (int j = 0; j < 4; ++j)
                    mma_tf32(acc[i][j], af[i], bf[j]);
        }
        if (tt + 1 < T) {
            const int nxt = cur ^ 1;
            uint4 u;
            u.x = f2tf(a1R.x); u.y = f2tf(a1R.y); u.z = f2tf(a1R.z); u.w = f2tf(a1R.w);
            *(uint4*)&As[nxt][ar][akq] = u;
            u.x = f2tf(a2R.x); u.y = f2tf(a2R.y); u.z = f2tf(a2R.z); u.w = f2tf(a2R.w);
            *(uint4*)&As[nxt][ar + 64][akq] = u;
            u.x = f2tf(bR.x); u.y = f2tf(bR.y); u.z = f2tf(bR.z); u.w = f2tf(bR.w);
            *(uint4*)&Bs[nxt][bk][bnq] = u;
            __syncthreads();
        }
    }

    // epilogue
    #pragma unroll
    for (int i = 0; i < 2; ++i) {
        const int r0 = bM + wm + (i << 4) + g;
        const int r1 = r0 + 8;
        #pragma unroll
        for (int j = 0; j < 4; ++j) {
            const int col = bN + wn + (j << 3) + (t << 1);
            if (col >= N) continue;
            float b0v = 0.f, b1v = 0.f;
            if (addBias) {
                float2 bb = *(const float2*)(bias + col);
                b0v = bb.x; b1v = bb.y;
            }
            float c0 = acc[i][j][0] + b0v, c1 = acc[i][j][1] + b1v;
            float c2 = acc[i][j][2] + b0v, c3 = acc[i][j][3] + b1v;
            if (act) { c0 = gelu_f(c0); c1 = gelu_f(c1); c2 = gelu_f(c2); c3 = gelu_f(c3); }
            if (r0 < M) *(float2*)(C + (size_t)r0 * N + col) = make_float2(c0, c1);
            if (r1 < M) *(float2*)(C + (size_t)r1 * N + col) = make_float2(c2, c3);
        }
    }
}

// ---------------- GEMM wrappers ----------------
__global__ void __launch_bounds__(256) gemm_std(
    const float* __restrict__ A, const float* __restrict__ B,
    const float* __restrict__ bias, float* __restrict__ C,
    int M, int N, int K, int act)
{
    int bM = blockIdx.y * GBM;
    if (bM >= M) return;
    gemm_core(A, B, bias, C, M, N, K, 0, K, bM, blockIdx.x * GBN, act, 1);
}

__global__ void __launch_bounds__(256) gemm_splitk(
    const float* __restrict__ A, const float* __restrict__ B,
    float* __restrict__ C, int M, int N, int K, int sk)
{
    int bM = blockIdx.y * GBM;
    if (bM >= M) return;
    int z = blockIdx.z;
    gemm_core(A, B, nullptr, C + (size_t)z * M * N, M, N, K, z * sk, sk,
              bM, blockIdx.x * GBN, 0, 0);
}

__constant__ int c_Ms[3] = {500, 250, 125};
__constant__ int c_ro[3] = {0, 500, 750};

__global__ void __launch_bounds__(256) gemm_qkv(
    const float* __restrict__ h, const float* __restrict__ pool,
    const float* __restrict__ Wq, const float* __restrict__ Wk, const float* __restrict__ Wv,
    const float* __restrict__ bq, const float* __restrict__ bk, const float* __restrict__ bv,
    float* __restrict__ q, float* __restrict__ k, float* __restrict__ v)
{
    int z = blockIdx.z;
    int si = z / 3, which = z - si * 3;
    int M = c_Ms[si];
    int bM = blockIdx.y * GBM;
    if (bM >= M) return;
    const float* A = (si == 0) ? h : (pool + (si == 2 ? 250 * DMODEL : 0));
    const float* W = (which == 0) ? Wq : (which == 1) ? Wk : Wv;
    const float* bb = (which == 0) ? bq : (which == 1) ? bk : bv;
    float* Cb = (which == 0) ? q : (which == 1) ? k : v;
    gemm_core(A, W + (size_t)si * DMODEL * QKVD, bb + (size_t)si * QKVD,
              Cb + (size_t)c_ro[si] * QKVD, M, QKVD, DMODEL, 0, DMODEL,
              bM, blockIdx.x * GBN, 0, 1);
}

__global__ void __launch_bounds__(256) gemm_wo(
    const float* __restrict__ o, const float* __restrict__ Wo,
    const float* __restrict__ bo, float* __restrict__ ao)
{
    int si = blockIdx.z;
    int M = c_Ms[si];
    int bM = blockIdx.y * GBM;
    if (bM >= M) return;
    gemm_core(o + (size_t)c_ro[si] * QKVD, Wo + (size_t)si * QKVD * DMODEL,
              bo + (size_t)si * DMODEL, ao + (size_t)c_ro[si] * DMODEL,
              M, DMODEL, QKVD, 0, QKVD, bM, blockIdx.x * GBN, 0, 1);
}

// ---------------- small kernels ----------------
__global__ void colsum_kernel(const float* __restrict__ W, float* __restrict__ cs) {
    int d = threadIdx.x;
    float s = 0.f;
    #pragma unroll 4
    for (int p = 0; p < 100; p++) s += W[p * DMODEL + d];
    cs[d] = s;
}

__global__ void init_h_kernel(const float* __restrict__ cs, const float* __restrict__ ln_in_b,
                              const float* __restrict__ patch_b, const float* __restrict__ pos,
                              float* __restrict__ h) {
    int n = blockIdx.x, d = threadIdx.x;
    h[n * DMODEL + d] = ln_in_b[0] * cs[d] + patch_b[d] + pos[n * DMODEL + d];
}

__global__ void pool_kernel(const float* __restrict__ h, float* __restrict__ p) {
    int i = blockIdx.x, d = threadIdx.x;
    if (i < 250) {
        p[i * DMODEL + d] = 0.5f * (h[(2 * i) * DMODEL + d] + h[(2 * i + 1) * DMODEL + d]);
    } else {
        int j = i - 250;
        p[i * DMODEL + d] = 0.25f * (h[(4 * j) * DMODEL + d] + h[(4 * j + 1) * DMODEL + d] +
                                     h[(4 * j + 2) * DMODEL + d] + h[(4 * j + 3) * DMODEL + d]);
    }
}

// ---------------- attention: block per (scale, head, 8 queries) ----------------
// 256 threads = 8 warps; warp = one query; lane = one key per 32-key tile.
// K/V tiles staged in smem; no inner-loop shuffles.
__global__ void __launch_bounds__(256) attn_kernel(
    const float* __restrict__ q, const float* __restrict__ k,
    const float* __restrict__ v, float* __restrict__ o)
{
    __shared__ float Ks[32][34];
    __shared__ float Vs[32][34];
    __shared__ float OS[8][32][34];

    const int b = blockIdx.x;
    int Ns, ro, h, qg;
    if (b < 315)      { Ns = 500; ro = 0;   h = b / 63;  qg = b % 63; }
    else if (b < 475) { int c = b - 315; Ns = 250; ro = 500; h = c / 32; qg = c % 32; }
    else              { int c = b - 475; Ns = 125; ro = 750; h = c / 16; qg = c % 16; }

    const int wid = threadIdx.x >> 5;
    const int lane = threadIdx.x & 31;
    const int n = qg * 8 + wid;
    const bool valid = n < Ns;
    const int nq = valid ? n : (Ns - 1);
    const float scale = 0.1767766952966369f;  // 1/sqrt(32)

    // q in registers (identical across lanes), pre-scaled
    float2 qr[16];
    {
        const float2* qp = (const float2*)(q + (size_t)(ro + nq) * QKVD + h * KDIM);
        #pragma unroll
        for (int i = 0; i < 16; i++) {
            float2 tq = qp[i];
            qr[i] = make_float2(tq.x * scale, tq.y * scale);
        }
    }

    float mmax = -INFINITY, ssum = 0.f;
    float oa[32];
    #pragma unroll
    for (int d = 0; d < 32; d++) oa[d] = 0.f;

    const int nt = (Ns + 31) >> 5;
    for (int tt = 0; tt < nt; tt++) {
        const int kt = tt << 5;
        {   // cooperative tile load: thread -> (row m, dim-quad dq)
            const int m = threadIdx.x >> 3;
            const int dq = (threadIdx.x & 7) << 2;
            const int row = min(kt + m, Ns - 1);
            const float4 kk = *(const float4*)(k + (size_t)(ro + row) * QKVD + h * KDIM + dq);
            const float4 vv = *(const float4*)(v + (size_t)(ro + row) * QKVD + h * KDIM + dq);
            *(float2*)&Ks[m][dq]     = make_float2(kk.x, kk.y);
            *(float2*)&Ks[m][dq + 2] = make_float2(kk.z, kk.w);
            *(float2*)&Vs[m][dq]     = make_float2(vv.x, vv.y);
            *(float2*)&Vs[m][dq + 2] = make_float2(vv.z, vv.w);
        }
        __syncthreads();

        float s0 = 0.f, s1 = 0.f;
        #pragma unroll
        for (int i = 0; i < 16; i++) {
            float2 kk = *(const float2*)&Ks[lane][2 * i];
            s0 = fmaf(qr[i].x, kk.x, s0);
            s1 = fmaf(qr[i].y, kk.y, s1);
        }
        float s = s0 + s1;
        if (kt + lane >= Ns) s = -INFINITY;

        float nm = fmaxf(mmax, s);
        float corr = __expf(mmax - nm);    // exp(-inf)=0 handles first tile
        float p = __expf(s - nm);
        ssum = ssum * corr + p;
        #pragma unroll
        for (int i = 0; i < 16; i++) {
            float2 vv = *(const float2*)&Vs[lane][2 * i];
            oa[2 * i]     = oa[2 * i]     * corr + p * vv.x;
            oa[2 * i + 1] = oa[2 * i + 1] * corr + p * vv.y;
        }
        mmax = nm;
        __syncthreads();
    }

    // cross-lane softmax merge
    float gm = mmax;
    #pragma unroll
    for (int off = 16; off; off >>= 1) gm = fmaxf(gm, __shfl_xor_sync(0xffffffffu, gm, off));
    float c = __expf(mmax - gm);
    float ss = ssum * c;
    #pragma unroll
    for (int off = 16; off; off >>= 1) ss += __shfl_xor_sync(0xffffffffu, ss, off);

    #pragma unroll
    for (int i = 0; i < 16; i++)
        *(float2*)&OS[wid][lane][2 * i] = make_float2(oa[2 * i] * c, oa[2 * i + 1] * c);
    __syncwarp();

    float accd = 0.f;
    #pragma unroll
    for (int m = 0; m < 32; m++) accd += OS[wid][m][lane];
    if (valid)
        o[(size_t)(ro + n) * QKVD + h * KDIM + lane] = accd / ss;
}

__global__ void cat_kernel(const float* __restrict__ ao, float* __restrict__ cat) {
    int n = blockIdx.x, d = threadIdx.x;
    cat[n * CATD + d]        = ao[n * DMODEL + d];
    cat[n * CATD + 512 + d]  = ao[(500 + (n >> 1)) * DMODEL + d];
    cat[n * CATD + 1024 + d] = ao[(750 + (n >> 2)) * DMODEL + d];
}

// h[n,:] = LayerNorm(h[n,:] + bias + sum_{s<S} part[s][n,:]) * g + b
__global__ void reduce_add_ln_kernel(const float* __restrict__ part, int S,
                                     const float* __restrict__ bias,
                                     float* __restrict__ h,
                                     const float* __restrict__ g,
                                     const float* __restrict__ b) {
    int n = blockIdx.x, t = threadIdx.x;
    __shared__ float red[8];
    __shared__ float stat;
    float v0 = h[n * DMODEL + t]       + bias[t];
    float v1 = h[n * DMODEL + t + 256] + bias[t + 256];
    for (int s = 0; s < S; s++) {
        v0 += part[(size_t)s * NPATCH * DMODEL + n * DMODEL + t];
        v1 += part[(size_t)s * NPATCH * DMODEL + n * DMODEL + t + 256];
    }

    float s = v0 + v1;
    #pragma unroll
    for (int o = 16; o; o >>= 1) s += __shfl_xor_sync(0xffffffffu, s, o);
    if ((t & 31) == 0) red[t >> 5] = s;
    __syncthreads();
    if (t < 32) {
        float x = (t < 8) ? red[t] : 0.f;
        #pragma unroll
        for (int o = 4; o; o >>= 1) x += __shfl_xor_sync(0xffffffffu, x, o);
        if (t == 0) stat = x / (float)DMODEL;
    }
    __syncthreads();
    float mean = stat;
    float dd0 = v0 - mean, dd1 = v1 - mean;

    __syncthreads();
    float vs = dd0 * dd0 + dd1 * dd1;
    #pragma unroll
    for (int o = 16; o; o >>= 1) vs += __shfl_xor_sync(0xffffffffu, vs, o);
    if ((t & 31) == 0) red[t >> 5] = vs;
    __syncthreads();
    if (t < 32) {
        float x = (t < 8) ? red[t] : 0.f;
        #pragma unroll
        for (int o = 4; o; o >>= 1) x += __shfl_xor_sync(0xffffffffu, x, o);
        if (t == 0) stat = rsqrtf(x / (float)DMODEL + LN_EPS);
    }
    __syncthreads();
    float rstd = stat;
    h[n * DMODEL + t]       = dd0 * rstd * g[t]       + b[t];
    h[n * DMODEL + t + 256] = dd1 * rstd * g[t + 256] + b[t + 256];
}

__global__ void gpool_kernel(const float* __restrict__ h, float* __restrict__ g) {
    int d = threadIdx.x;
    float s = 0.f;
    for (int n = 0; n < NPATCH; n++) s += h[n * DMODEL + d];
    g[d] = s / (float)NPATCH;
}

__global__ void head_kernel(const float* __restrict__ g, const float* __restrict__ W,
                            const float* __restrict__ b, float* __restrict__ out) {
    __shared__ float gs[DMODEL];
    __shared__ float red[8];
    __shared__ float stat;
    int t = threadIdx.x;
    gs[t] = g[t]; gs[t + 256] = g[t + 256];
    __syncthreads();
    float acc = b[t];
    #pragma unroll 4
    for (int d = 0; d < DMODEL; d++) acc += gs[d] * W[d * NCLS + t];

    float m = acc;
    #pragma unroll
    for (int o = 16; o; o >>= 1) m = fmaxf(m, __shfl_xor_sync(0xffffffffu, m, o));
    if ((t & 31) == 0) red[t >> 5] = m;
    __syncthreads();
    if (t < 32) {
        float x = (t < 8) ? red[t] : -INFINITY;
        #pragma unroll
        for (int o = 4; o; o >>= 1) x = fmaxf(x, __shfl_xor_sync(0xffffffffu, x, o));
        if (t == 0) stat = x;
    }
    __syncthreads();
    float e = expf(acc - stat);
    __syncthreads();
    float s = e;
    #pragma unroll
    for (int o = 16; o; o >>= 1) s += __shfl_xor_sync(0xffffffffu, s, o);
    if ((t & 31) == 0) red[t >> 5] = s;
    __syncthreads();
    if (t < 32) {
        float x = (t < 8) ? red[t] : 0.f;
        #pragma unroll
        for (int o = 4; o; o >>= 1) x += __shfl_xor_sync(0xffffffffu, x, o);
        if (t == 0) stat = x;
    }
    __syncthreads();
    float p = e / stat;
    for (int bb = 0; bb < NBATCH; bb++) out[bb * NCLS + t] = p;
}

// ---------------- host launcher ----------------
extern "C" void kernel_launch(void* const* d_in, const int* in_sizes, int n_in,
                              void* d_out, int out_size) {
    const float* ln_in_b = (const float*)d_in[2];
    const float* patch_W = (const float*)d_in[3];
    const float* patch_b = (const float*)d_in[4];
    const float* pos_emb = (const float*)d_in[5];
    const float* Wq = (const float*)d_in[6];
    const float* bq = (const float*)d_in[7];
    const float* Wk = (const float*)d_in[8];
    const float* bk = (const float*)d_in[9];
    const float* Wv = (const float*)d_in[10];
    const float* bv = (const float*)d_in[11];
    const float* Wo = (const float*)d_in[12];
    const float* bo = (const float*)d_in[13];
    const float* Wc = (const float*)d_in[14];
    const float* bc = (const float*)d_in[15];
    const float* ln1_g = (const float*)d_in[16];
    const float* ln1_b = (const float*)d_in[17];
    const float* W1 = (const float*)d_in[18];
    const float* b1 = (const float*)d_in[19];
    const float* W2 = (const float*)d_in[20];
    const float* b2 = (const float*)d_in[21];
    const float* ln2_g = (const float*)d_in[22];
    const float* ln2_b = (const float*)d_in[23];
    const float* head_W = (const float*)d_in[24];
    const float* head_b = (const float*)d_in[25];
    float* out = (float*)d_out;

    float *hp, *pp, *qp, *kp, *vp, *op, *aop, *catp, *ffp, *partp, *csp, *gp;
    cudaGetSymbolAddress((void**)&hp,  d_h);
    cudaGetSymbolAddress((void**)&pp,  d_pool);
    cudaGetSymbolAddress((void**)&qp,  d_q);
    cudaGetSymbolAddress((void**)&kp,  d_k);
    cudaGetSymbolAddress((void**)&vp,  d_v);
    cudaGetSymbolAddress((void**)&op,  d_o);
    cudaGetSymbolAddress((void**)&aop, d_ao);
    cudaGetSymbolAddress((void**)&catp, d_cat);
    cudaGetSymbolAddress((void**)&ffp, d_ff);
    cudaGetSymbolAddress((void**)&partp, d_part);
    cudaGetSymbolAddress((void**)&csp, d_cs);
    cudaGetSymbolAddress((void**)&gp,  d_gv);

    colsum_kernel<<<1, DMODEL>>>(patch_W, csp);
    init_h_kernel<<<NPATCH, DMODEL>>>(csp, ln_in_b, patch_b, pos_emb, hp);

    for (int l = 0; l < NLAYER; l++) {
        size_t wqkv = (size_t)l * 3 * DMODEL * QKVD;
        size_t bqkv = (size_t)l * 3 * QKVD;
        size_t wwo  = (size_t)l * 3 * QKVD * DMODEL;
        size_t bwo  = (size_t)l * 3 * DMODEL;

        pool_kernel<<<375, DMODEL>>>(hp, pp);
        gemm_qkv<<<dim3(3, 4, 9), 256>>>(hp, pp,
            Wq + wqkv, Wk + wqkv, Wv + wqkv, bq + bqkv, bk + bqkv, bv + bqkv,
            qp, kp, vp);
        attn_kernel<<<555, 256>>>(qp, kp, vp, op);
        gemm_wo<<<dim3(8, 4, 3), 256>>>(op, Wo + wwo, bo + bwo, aop);
        cat_kernel<<<NPATCH, DMODEL>>>(aop, catp);

        // combine: split-K 6x256 -> partials -> fused reduce+bias+residual+LN
        gemm_splitk<<<dim3(8, 4, 6), 256>>>(catp, Wc + (size_t)l * CATD * DMODEL,
                                            partp, NPATCH, DMODEL, CATD, 256);
        reduce_add_ln_kernel<<<NPATCH, 256>>>(partp, 6, bc + (size_t)l * DMODEL, hp,
                                              ln1_g + l * DMODEL, ln1_b + l * DMODEL);

        // FFN
        gemm_std<<<dim3(32, 4), 256>>>(hp, W1 + (size_t)l * DMODEL * FFD,
                                       b1 + (size_t)l * FFD, ffp,
                                       NPATCH, FFD, DMODEL, 1);
        gemm_splitk<<<dim3(8, 4, 4), 256>>>(ffp, W2 + (size_t)l * FFD * DMODEL,
                                            partp, NPATCH, DMODEL, FFD, 512);
        reduce_add_ln_kernel<<<NPATCH, 256>>>(partp, 4, b2 + (size_t)l * DMODEL, hp,
                                              ln2_g + l * DMODEL, ln2_b + l * DMODEL);
    }

    gpool_kernel<<<1, DMODEL>>>(hp, gp);
    head_kernel<<<1, NCLS>>>(gp, head_W, head_b, out);
}

// round 6
// speedup vs baseline: 14.9247x; 1.2482x over previous
#include <cuda_runtime.h>
#include <cstdint>
#include <math.h>

// ---------------- problem constants ----------------
#define NPATCH 500
#define DMODEL 512
#define NHS    5
#define KDIM   32
#define QKVD   160
#define CATD   1536
#define FFD    2048
#define NLAYER 6
#define NBATCH 32
#define NCLS   256
#define LN_EPS 1e-3f
#define RTOT 875     // rows: scale1 [0,500), scale2 [500,750), scale4 [750,875)

#define GBM 128
#define GBN 64
#define NSTG 3

// ---------------- scratch ----------------
__device__ float d_h   [NPATCH * DMODEL];
__device__ float d_pool[375 * DMODEL];
__device__ float d_q   [RTOT * QKVD];
__device__ float d_k   [RTOT * QKVD];
__device__ float d_v   [RTOT * QKVD];
__device__ float d_o   [RTOT * QKVD];
__device__ float d_cat [NPATCH * CATD];
__device__ float d_ff  [NPATCH * FFD];
__device__ float d_part[6 * NPATCH * DMODEL];
__device__ float d_cs  [DMODEL];
__device__ float d_gv  [DMODEL];

// ---------------- helpers ----------------
__device__ __forceinline__ uint32_t smem_u32(const void* p) {
    return (uint32_t)__cvta_generic_to_shared(p);
}
__device__ __forceinline__ void cp16(uint32_t dst, const void* src, int sbytes) {
    asm volatile("cp.async.cg.shared.global [%0], [%1], 16, %2;\n"
                 :: "r"(dst), "l"(src), "r"(sbytes));
}
__device__ __forceinline__ void cp_commit() { asm volatile("cp.async.commit_group;\n"); }
__device__ __forceinline__ void mma_tf32(float* c, const uint32_t* a, const uint32_t* b) {
    asm volatile(
        "mma.sync.aligned.m16n8k8.row.col.f32.tf32.tf32.f32 "
        "{%0,%1,%2,%3}, {%4,%5,%6,%7}, {%8,%9}, {%0,%1,%2,%3};"
        : "+f"(c[0]), "+f"(c[1]), "+f"(c[2]), "+f"(c[3])
        : "r"(a[0]), "r"(a[1]), "r"(a[2]), "r"(a[3]), "r"(b[0]), "r"(b[1]));
}
__device__ __forceinline__ float gelu_f(float x) {
    return 0.5f * x * (1.f + erff(x * 0.70710678118654752f));
}

// ---------------- core GEMM tile (tf32 MMA, 3-stage cp.async, 256 thr, 128x64) ----
// 8 warps (4x2). Warp tile 32x32 (2 m-subtiles x 4 n-subtiles of m16n8k8).
// A row-major (lda), B row-major (N). kLen % 16 == 0, N % 4 == 0.
// Output rows replicated rep times into C with leading dim ldc.
__device__ __forceinline__ void gemm_core(
    const float* __restrict__ A, const float* __restrict__ B,
    const float* __restrict__ bias, float* __restrict__ C,
    int M, int N, int lda, int kOff, int kLen,
    int bM, int bN, int act, int addBias, int ldc, int rep)
{
    __shared__ uint32_t As[NSTG][GBM][20];   // [m][k] pad 20 (conflict-free frags)
    __shared__ uint32_t Bs[NSTG][16][72];    // [k][n] pad 8

    const int tid  = threadIdx.x;
    const int lane = tid & 31;
    const int warp = tid >> 5;
    const int wm = (warp & 3) << 5;       // 0,32,64,96
    const int wn = (warp >> 2) << 5;      // 0,32
    const int g = lane >> 2;              // 0..7
    const int t = lane & 3;               // 0..3

    // A: rows ar, ar+64 ; k-quad akq
    const int ar  = tid >> 2;             // 0..63
    const int akq = (tid & 3) << 2;       // 0,4,8,12
    const int m1 = min(bM + ar, M - 1);
    const int m2 = min(bM + ar + 64, M - 1);
    const float* aSrc1 = A + (size_t)m1 * lda + kOff + akq;
    const float* aSrc2 = A + (size_t)m2 * lda + kOff + akq;

    // B: k-row bk ; n-quad bnq (one float4 per thread)
    const int bk  = tid >> 4;             // 0..15
    const int bnq = (tid & 15) << 2;      // 0..60
    const int bBytes = ((bN + bnq) < N) ? 16 : 0;   // zero-fill OOB columns
    const float* bSrc = B + (size_t)(kOff + bk) * N + bN + bnq;

    uint32_t aD1[NSTG], aD2[NSTG], bD[NSTG];
    #pragma unroll
    for (int s = 0; s < NSTG; ++s) {
        aD1[s] = smem_u32(&As[s][ar][akq]);
        aD2[s] = smem_u32(&As[s][ar + 64][akq]);
        bD[s]  = smem_u32(&Bs[s][bk][bnq]);
    }

    const int T = kLen >> 4;

    // prologue: stages 0,1
    #pragma unroll
    for (int p = 0; p < 2; ++p) {
        const int ko = p << 4;
        cp16(aD1[p], aSrc1 + ko, 16);
        cp16(aD2[p], aSrc2 + ko, 16);
        cp16(bD[p], bSrc + (size_t)ko * N, bBytes);
        cp_commit();
    }

    float acc[2][4][4] = {};

    int stage = 0;
    for (int tt = 0; tt < T; ++tt) {
        if (tt + 1 < T) { asm volatile("cp.async.wait_group 1;\n"); }
        else            { asm volatile("cp.async.wait_group 0;\n"); }
        __syncthreads();

        if (tt + 2 < T) {   // issue stage tt+2 (buffer freed by the sync above)
            const int ns = (stage + 2 >= NSTG) ? stage + 2 - NSTG : stage + 2;
            const int ko = (tt + 2) << 4;
            cp16(aD1[ns], aSrc1 + ko, 16);
            cp16(aD2[ns], aSrc2 + ko, 16);
            cp16(bD[ns], bSrc + (size_t)ko * N, bBytes);
            cp_commit();
        }

        #pragma unroll
        for (int ks = 0; ks < 2; ++ks) {
            const int k0 = ks << 3;
            uint32_t af[2][4];
            #pragma unroll
            for (int i = 0; i < 2; ++i) {
                const int r = wm + (i << 4) + g;
                af[i][0] = As[stage][r][k0 + t];
                af[i][1] = As[stage][r + 8][k0 + t];
                af[i][2] = As[stage][r][k0 + t + 4];
                af[i][3] = As[stage][r + 8][k0 + t + 4];
            }
            uint32_t bf[4][2];
            #pragma unroll
            for (int j = 0; j < 4; ++j) {
                const int c = wn + (j << 3) + g;
                bf[j][0] = Bs[stage][k0 + t][c];
                bf[j][1] = Bs[stage][k0 + t + 4][c];
            }
            #pragma unroll
            for (int i = 0; i < 2; ++i)
                #pragma unroll
                for (int j = 0; j < 4; ++j)
                    mma_tf32(acc[i][j], af[i], bf[j]);
        }
        stage = (stage + 1 >= NSTG) ? 0 : stage + 1;
    }

    // epilogue
    #pragma unroll
    for (int i = 0; i < 2; ++i) {
        const int r0 = bM + wm + (i << 4) + g;
        const int r1 = r0 + 8;
        #pragma unroll
        for (int j = 0; j < 4; ++j) {
            const int col = bN + wn + (j << 3) + (t << 1);
            if (col >= N) continue;
            float b0v = 0.f, b1v = 0.f;
            if (addBias) {
                float2 bb = *(const float2*)(bias + col);
                b0v = bb.x; b1v = bb.y;
            }
            float c0 = acc[i][j][0] + b0v, c1 = acc[i][j][1] + b1v;
            float c2 = acc[i][j][2] + b0v, c3 = acc[i][j][3] + b1v;
            if (act) { c0 = gelu_f(c0); c1 = gelu_f(c1); c2 = gelu_f(c2); c3 = gelu_f(c3); }
            if (r0 < M)
                for (int rr = 0; rr < rep; ++rr)
                    *(float2*)(C + (size_t)(r0 * rep + rr) * ldc + col) = make_float2(c0, c1);
            if (r1 < M)
                for (int rr = 0; rr < rep; ++rr)
                    *(float2*)(C + (size_t)(r1 * rep + rr) * ldc + col) = make_float2(c2, c3);
        }
    }
}

// ---------------- GEMM wrappers ----------------
__global__ void __launch_bounds__(256) gemm_std(
    const float* __restrict__ A, const float* __restrict__ B,
    const float* __restrict__ bias, float* __restrict__ C,
    int M, int N, int K, int act)
{
    int bM = blockIdx.y * GBM;
    if (bM >= M) return;
    gemm_core(A, B, bias, C, M, N, K, 0, K, bM, blockIdx.x * GBN, act, 1, N, 1);
}

__global__ void __launch_bounds__(256) gemm_splitk(
    const float* __restrict__ A, const float* __restrict__ B,
    float* __restrict__ C, int M, int N, int K, int sk)
{
    int bM = blockIdx.y * GBM;
    if (bM >= M) return;
    int z = blockIdx.z;
    gemm_core(A, B, nullptr, C + (size_t)z * M * N, M, N, K, z * sk, sk,
              bM, blockIdx.x * GBN, 0, 0, N, 1);
}

__constant__ int c_Ms[3]  = {500, 250, 125};
__constant__ int c_ro[3]  = {0, 500, 750};
__constant__ int c_sc[3]  = {1, 2, 4};

__global__ void __launch_bounds__(256) gemm_qkv(
    const float* __restrict__ h, const float* __restrict__ pool,
    const float* __restrict__ Wq, const float* __restrict__ Wk, const float* __restrict__ Wv,
    const float* __restrict__ bq, const float* __restrict__ bk, const float* __restrict__ bv,
    float* __restrict__ q, float* __restrict__ k, float* __restrict__ v)
{
    int z = blockIdx.z;
    int si = z / 3, which = z - si * 3;
    int M = c_Ms[si];
    int bM = blockIdx.y * GBM;
    if (bM >= M) return;
    const float* A = (si == 0) ? h : (pool + (si == 2 ? 250 * DMODEL : 0));
    const float* W = (which == 0) ? Wq : (which == 1) ? Wk : Wv;
    const float* bb = (which == 0) ? bq : (which == 1) ? bk : bv;
    float* Cb = (which == 0) ? q : (which == 1) ? k : v;
    gemm_core(A, W + (size_t)si * DMODEL * QKVD, bb + (size_t)si * QKVD,
              Cb + (size_t)c_ro[si] * QKVD, M, QKVD, DMODEL, 0, DMODEL,
              bM, blockIdx.x * GBN, 0, 1, QKVD, 1);
}

// Wo with fused upsample+concat: writes directly into cat buffer.
__global__ void __launch_bounds__(256) gemm_wo(
    const float* __restrict__ o, const float* __restrict__ Wo,
    const float* __restrict__ bo, float* __restrict__ cat)
{
    int si = blockIdx.z;
    int M = c_Ms[si];
    int bM = blockIdx.y * GBM;
    if (bM >= M) return;
    gemm_core(o + (size_t)c_ro[si] * QKVD, Wo + (size_t)si * QKVD * DMODEL,
              bo + (size_t)si * DMODEL, cat + (size_t)si * DMODEL,
              M, DMODEL, QKVD, 0, QKVD, bM, blockIdx.x * GBN, 0, 1,
              CATD, c_sc[si]);
}

// ---------------- small kernels ----------------
__global__ void colsum_kernel(const float* __restrict__ W, float* __restrict__ cs) {
    int d = threadIdx.x;
    float s = 0.f;
    #pragma unroll 4
    for (int p = 0; p < 100; p++) s += W[p * DMODEL + d];
    cs[d] = s;
}

__global__ void init_h_kernel(const float* __restrict__ cs, const float* __restrict__ ln_in_b,
                              const float* __restrict__ patch_b, const float* __restrict__ pos,
                              float* __restrict__ h) {
    int n = blockIdx.x, d = threadIdx.x;
    h[n * DMODEL + d] = ln_in_b[0] * cs[d] + patch_b[d] + pos[n * DMODEL + d];
}

__global__ void pool_kernel(const float* __restrict__ h, float* __restrict__ p) {
    int i = blockIdx.x, d = threadIdx.x;
    if (i < 250) {
        p[i * DMODEL + d] = 0.5f * (h[(2 * i) * DMODEL + d] + h[(2 * i + 1) * DMODEL + d]);
    } else {
        int j = i - 250;
        p[i * DMODEL + d] = 0.25f * (h[(4 * j) * DMODEL + d] + h[(4 * j + 1) * DMODEL + d] +
                                     h[(4 * j + 2) * DMODEL + d] + h[(4 * j + 3) * DMODEL + d]);
    }
}

// ---------------- attention: block per (scale, head, 8 queries) ----------------
__global__ void __launch_bounds__(256) attn_kernel(
    const float* __restrict__ q, const float* __restrict__ k,
    const float* __restrict__ v, float* __restrict__ o)
{
    __shared__ float Ks[32][34];
    __shared__ float Vs[32][34];
    __shared__ float OS[8][32][34];

    const int b = blockIdx.x;
    int Ns, ro, h, qg;
    if (b < 315)      { Ns = 500; ro = 0;   h = b / 63;  qg = b % 63; }
    else if (b < 475) { int c = b - 315; Ns = 250; ro = 500; h = c / 32; qg = c % 32; }
    else              { int c = b - 475; Ns = 125; ro = 750; h = c / 16; qg = c % 16; }

    const int wid = threadIdx.x >> 5;
    const int lane = threadIdx.x & 31;
    const int n = qg * 8 + wid;
    const bool valid = n < Ns;
    const int nq = valid ? n : (Ns - 1);
    const float scale = 0.1767766952966369f;  // 1/sqrt(32)

    float2 qr[16];
    {
        const float2* qp = (const float2*)(q + (size_t)(ro + nq) * QKVD + h * KDIM);
        #pragma unroll
        for (int i = 0; i < 16; i++) {
            float2 tq = qp[i];
            qr[i] = make_float2(tq.x * scale, tq.y * scale);
        }
    }

    float mmax = -INFINITY, ssum = 0.f;
    float oa[32];
    #pragma unroll
    for (int d = 0; d < 32; d++) oa[d] = 0.f;

    const int nt = (Ns + 31) >> 5;
    for (int tt = 0; tt < nt; tt++) {
        const int kt = tt << 5;
        {
            const int m = threadIdx.x >> 3;
            const int dq = (threadIdx.x & 7) << 2;
            const int row = min(kt + m, Ns - 1);
            const float4 kk = *(const float4*)(k + (size_t)(ro + row) * QKVD + h * KDIM + dq);
            const float4 vv = *(const float4*)(v + (size_t)(ro + row) * QKVD + h * KDIM + dq);
            *(float2*)&Ks[m][dq]     = make_float2(kk.x, kk.y);
            *(float2*)&Ks[m][dq + 2] = make_float2(kk.z, kk.w);
            *(float2*)&Vs[m][dq]     = make_float2(vv.x, vv.y);
            *(float2*)&Vs[m][dq + 2] = make_float2(vv.z, vv.w);
        }
        __syncthreads();

        float s0 = 0.f, s1 = 0.f;
        #pragma unroll
        for (int i = 0; i < 16; i++) {
            float2 kk = *(const float2*)&Ks[lane][2 * i];
            s0 = fmaf(qr[i].x, kk.x, s0);
            s1 = fmaf(qr[i].y, kk.y, s1);
        }
        float s = s0 + s1;
        if (kt + lane >= Ns) s = -INFINITY;

        float nm = fmaxf(mmax, s);
        float corr = __expf(mmax - nm);
        float p = __expf(s - nm);
        ssum = ssum * corr + p;
        #pragma unroll
        for (int i = 0; i < 16; i++) {
            float2 vv = *(const float2*)&Vs[lane][2 * i];
            oa[2 * i]     = oa[2 * i]     * corr + p * vv.x;
            oa[2 * i + 1] = oa[2 * i + 1] * corr + p * vv.y;
        }
        mmax = nm;
        __syncthreads();
    }

    float gm = mmax;
    #pragma unroll
    for (int off = 16; off; off >>= 1) gm = fmaxf(gm, __shfl_xor_sync(0xffffffffu, gm, off));
    float c = __expf(mmax - gm);
    float ss = ssum * c;
    #pragma unroll
    for (int off = 16; off; off >>= 1) ss += __shfl_xor_sync(0xffffffffu, ss, off);

    #pragma unroll
    for (int i = 0; i < 16; i++)
        *(float2*)&OS[wid][lane][2 * i] = make_float2(oa[2 * i] * c, oa[2 * i + 1] * c);
    __syncwarp();

    float accd = 0.f;
    #pragma unroll
    for (int m = 0; m < 32; m++) accd += OS[wid][m][lane];
    if (valid)
        o[(size_t)(ro + n) * QKVD + h * KDIM + lane] = accd / ss;
}

// h[n,:] = LayerNorm(h[n,:] + bias + sum_{s<S} part[s][n,:]) * g + b
__global__ void reduce_add_ln_kernel(const float* __restrict__ part, int S,
                                     const float* __restrict__ bias,
                                     float* __restrict__ h,
                                     const float* __restrict__ g,
                                     const float* __restrict__ b) {
    int n = blockIdx.x, t = threadIdx.x;
    __shared__ float red[8];
    __shared__ float stat;
    float v0 = h[n * DMODEL + t]       + bias[t];
    float v1 = h[n * DMODEL + t + 256] + bias[t + 256];
    for (int s = 0; s < S; s++) {
        v0 += part[(size_t)s * NPATCH * DMODEL + n * DMODEL + t];
        v1 += part[(size_t)s * NPATCH * DMODEL + n * DMODEL + t + 256];
    }

    float s = v0 + v1;
    #pragma unroll
    for (int o = 16; o; o >>= 1) s += __shfl_xor_sync(0xffffffffu, s, o);
    if ((t & 31) == 0) red[t >> 5] = s;
    __syncthreads();
    if (t < 32) {
        float x = (t < 8) ? red[t] : 0.f;
        #pragma unroll
        for (int o = 4; o; o >>= 1) x += __shfl_xor_sync(0xffffffffu, x, o);
        if (t == 0) stat = x / (float)DMODEL;
    }
    __syncthreads();
    float mean = stat;
    float dd0 = v0 - mean, dd1 = v1 - mean;

    __syncthreads();
    float vs = dd0 * dd0 + dd1 * dd1;
    #pragma unroll
    for (int o = 16; o; o >>= 1) vs += __shfl_xor_sync(0xffffffffu, vs, o);
    if ((t & 31) == 0) red[t >> 5] = vs;
    __syncthreads();
    if (t < 32) {
        float x = (t < 8) ? red[t] : 0.f;
        #pragma unroll
        for (int o = 4; o; o >>= 1) x += __shfl_xor_sync(0xffffffffu, x, o);
        if (t == 0) stat = rsqrtf(x / (float)DMODEL + LN_EPS);
    }
    __syncthreads();
    float rstd = stat;
    h[n * DMODEL + t]       = dd0 * rstd * g[t]       + b[t];
    h[n * DMODEL + t + 256] = dd1 * rstd * g[t + 256] + b[t + 256];
}

__global__ void gpool_kernel(const float* __restrict__ h, float* __restrict__ g) {
    int d = threadIdx.x;
    float s = 0.f;
    for (int n = 0; n < NPATCH; n++) s += h[n * DMODEL + d];
    g[d] = s / (float)NPATCH;
}

__global__ void head_kernel(const float* __restrict__ g, const float* __restrict__ W,
                            const float* __restrict__ b, float* __restrict__ out) {
    __shared__ float gs[DMODEL];
    __shared__ float red[8];
    __shared__ float stat;
    int t = threadIdx.x;
    gs[t] = g[t]; gs[t + 256] = g[t + 256];
    __syncthreads();
    float acc = b[t];
    #pragma unroll 4
    for (int d = 0; d < DMODEL; d++) acc += gs[d] * W[d * NCLS + t];

    float m = acc;
    #pragma unroll
    for (int o = 16; o; o >>= 1) m = fmaxf(m, __shfl_xor_sync(0xffffffffu, m, o));
    if ((t & 31) == 0) red[t >> 5] = m;
    __syncthreads();
    if (t < 32) {
        float x = (t < 8) ? red[t] : -INFINITY;
        #pragma unroll
        for (int o = 4; o; o >>= 1) x = fmaxf(x, __shfl_xor_sync(0xffffffffu, x, o));
        if (t == 0) stat = x;
    }
    __syncthreads();
    float e = expf(acc - stat);
    __syncthreads();
    float s = e;
    #pragma unroll
    for (int o = 16; o; o >>= 1) s += __shfl_xor_sync(0xffffffffu, s, o);
    if ((t & 31) == 0) red[t >> 5] = s;
    __syncthreads();
    if (t < 32) {
        float x = (t < 8) ? red[t] : 0.f;
        #pragma unroll
        for (int o = 4; o; o >>= 1) x += __shfl_xor_sync(0xffffffffu, x, o);
        if (t == 0) stat = x;
    }
    __syncthreads();
    float p = e / stat;
    for (int bb = 0; bb < NBATCH; bb++) out[bb * NCLS + t] = p;
}

// ---------------- host launcher ----------------
extern "C" void kernel_launch(void* const* d_in, const int* in_sizes, int n_in,
                              void* d_out, int out_size) {
    const float* ln_in_b = (const float*)d_in[2];
    const float* patch_W = (const float*)d_in[3];
    const float* patch_b = (const float*)d_in[4];
    const float* pos_emb = (const float*)d_in[5];
    const float* Wq = (const float*)d_in[6];
    const float* bq = (const float*)d_in[7];
    const float* Wk = (const float*)d_in[8];
    const float* bk = (const float*)d_in[9];
    const float* Wv = (const float*)d_in[10];
    const float* bv = (const float*)d_in[11];
    const float* Wo = (const float*)d_in[12];
    const float* bo = (const float*)d_in[13];
    const float* Wc = (const float*)d_in[14];
    const float* bc = (const float*)d_in[15];
    const float* ln1_g = (const float*)d_in[16];
    const float* ln1_b = (const float*)d_in[17];
    const float* W1 = (const float*)d_in[18];
    const float* b1 = (const float*)d_in[19];
    const float* W2 = (const float*)d_in[20];
    const float* b2 = (const float*)d_in[21];
    const float* ln2_g = (const float*)d_in[22];
    const float* ln2_b = (const float*)d_in[23];
    const float* head_W = (const float*)d_in[24];
    const float* head_b = (const float*)d_in[25];
    float* out = (float*)d_out;

    float *hp, *pp, *qp, *kp, *vp, *op, *catp, *ffp, *partp, *csp, *gp;
    cudaGetSymbolAddress((void**)&hp,  d_h);
    cudaGetSymbolAddress((void**)&pp,  d_pool);
    cudaGetSymbolAddress((void**)&qp,  d_q);
    cudaGetSymbolAddress((void**)&kp,  d_k);
    cudaGetSymbolAddress((void**)&vp,  d_v);
    cudaGetSymbolAddress((void**)&op,  d_o);
    cudaGetSymbolAddress((void**)&catp, d_cat);
    cudaGetSymbolAddress((void**)&ffp, d_ff);
    cudaGetSymbolAddress((void**)&partp, d_part);
    cudaGetSymbolAddress((void**)&csp, d_cs);
    cudaGetSymbolAddress((void**)&gp,  d_gv);

    colsum_kernel<<<1, DMODEL>>>(patch_W, csp);
    init_h_kernel<<<NPATCH, DMODEL>>>(csp, ln_in_b, patch_b, pos_emb, hp);

    for (int l = 0; l < NLAYER; l++) {
        size_t wqkv = (size_t)l * 3 * DMODEL * QKVD;
        size_t bqkv = (size_t)l * 3 * QKVD;
        size_t wwo  = (size_t)l * 3 * QKVD * DMODEL;
        size_t bwo  = (size_t)l * 3 * DMODEL;

        pool_kernel<<<375, DMODEL>>>(hp, pp);
        gemm_qkv<<<dim3(3, 4, 9), 256>>>(hp, pp,
            Wq + wqkv, Wk + wqkv, Wv + wqkv, bq + bqkv, bk + bqkv, bv + bqkv,
            qp, kp, vp);
        attn_kernel<<<555, 256>>>(qp, kp, vp, op);
        gemm_wo<<<dim3(8, 4, 3), 256>>>(op, Wo + wwo, bo + bwo, catp);

        // combine: split-K 6x256 -> partials -> fused reduce+bias+residual+LN
        gemm_splitk<<<dim3(8, 4, 6), 256>>>(catp, Wc + (size_t)l * CATD * DMODEL,
                                            partp, NPATCH, DMODEL, CATD, 256);
        reduce_add_ln_kernel<<<NPATCH, 256>>>(partp, 6, bc + (size_t)l * DMODEL, hp,
                                              ln1_g + l * DMODEL, ln1_b + l * DMODEL);

        // FFN
        gemm_std<<<dim3(32, 4), 256>>>(hp, W1 + (size_t)l * DMODEL * FFD,
                                       b1 + (size_t)l * FFD, ffp,
                                       NPATCH, FFD, DMODEL, 1);
        gemm_splitk<<<dim3(8, 4, 4), 256>>>(ffp, W2 + (size_t)l * FFD * DMODEL,
                                            partp, NPATCH, DMODEL, FFD, 512);
        reduce_add_ln_kernel<<<NPATCH, 256>>>(partp, 4, b2 + (size_t)l * DMODEL, hp,
                                              ln2_g + l * DMODEL, ln2_b + l * DMODEL);
    }

    gpool_kernel<<<1, DMODEL>>>(hp, gp);
    head_kernel<<<1, NCLS>>>(gp, head_W, head_b, out);
}

// round 7
// speedup vs baseline: 15.6931x; 1.0515x over previous
#include <cuda_runtime.h>
#include <cstdint>
#include <math.h>

// ---------------- problem constants ----------------
#define NPATCH 500
#define DMODEL 512
#define NHS    5
#define KDIM   32
#define QKVD   160
#define CATD   1536
#define FFD    2048
#define NLAYER 6
#define NBATCH 32
#define NCLS   256
#define LN_EPS 1e-3f
#define RTOT 875     // rows: scale1 [0,500), scale2 [500,750), scale4 [750,875)

#define GBM 64
#define GBN 64
#define GBK 32
#define NSTG 3
// dynamic smem layout (uint32 words):
//   As(s,m,k) = sm[s*2304 + m*36 + k]          (64 x pad36)
//   Bs(s,k,n) = sm[6912 + s*2304 + k*72 + n]   (32 x pad72)
#define A_STW 2304
#define B_BASE 6912
#define SMEMB 55296

// ---------------- scratch ----------------
__device__ float d_h   [NPATCH * DMODEL];
__device__ float d_pool[375 * DMODEL];
__device__ float d_q   [RTOT * QKVD];
__device__ float d_k   [RTOT * QKVD];
__device__ float d_v   [RTOT * QKVD];
__device__ float d_o   [RTOT * QKVD];
__device__ float d_cat [NPATCH * CATD];
__device__ float d_ff  [NPATCH * FFD];
__device__ float d_part[8 * NPATCH * DMODEL];
__device__ float d_cs  [DMODEL];

// ---------------- helpers ----------------
__device__ __forceinline__ uint32_t smem_u32(const void* p) {
    return (uint32_t)__cvta_generic_to_shared(p);
}
__device__ __forceinline__ void cp16(uint32_t dst, const void* src, int sbytes) {
    asm volatile("cp.async.cg.shared.global [%0], [%1], 16, %2;\n"
                 :: "r"(dst), "l"(src), "r"(sbytes));
}
__device__ __forceinline__ void cp_commit() { asm volatile("cp.async.commit_group;\n"); }
__device__ __forceinline__ void mma_tf32(float* c, const uint32_t* a, const uint32_t* b) {
    asm volatile(
        "mma.sync.aligned.m16n8k8.row.col.f32.tf32.tf32.f32 "
        "{%0,%1,%2,%3}, {%4,%5,%6,%7}, {%8,%9}, {%0,%1,%2,%3};"
        : "+f"(c[0]), "+f"(c[1]), "+f"(c[2]), "+f"(c[3])
        : "r"(a[0]), "r"(a[1]), "r"(a[2]), "r"(a[3]), "r"(b[0]), "r"(b[1]));
}
__device__ __forceinline__ float gelu_f(float x) {
    return 0.5f * x * (1.f + erff(x * 0.70710678118654752f));
}

// ---------------- core GEMM tile (tf32 MMA, 3-stage cp.async, 256 thr, 64x64x32) ----
// 8 warps (2x4). Warp tile 32x16 (2 m-subtiles x 2 n-subtiles of m16n8k8).
// A row-major (lda), B row-major (N). kLen % 32 == 0, N % 4 == 0.
// Output rows replicated rep times into C with leading dim ldc.
__device__ __forceinline__ void gemm_core(
    const float* __restrict__ A, const float* __restrict__ B,
    const float* __restrict__ bias, float* __restrict__ C,
    int M, int N, int lda, int kOff, int kLen,
    int bM, int bN, int act, int addBias, int ldc, int rep)
{
    extern __shared__ uint32_t sm[];

    const int tid  = threadIdx.x;
    const int lane = tid & 31;
    const int warp = tid >> 5;
    const int wm = (warp & 1) << 5;       // 0,32
    const int wn = (warp >> 1) << 4;      // 0,16,32,48
    const int g = lane >> 2;              // 0..7
    const int t = lane & 3;               // 0..3

    // A global->smem: row ar (0..63), k quads akq, akq+16
    const int ar  = tid >> 2;             // 0..63
    const int akq = (tid & 3) << 2;       // 0,4,8,12
    const int mrow = min(bM + ar, M - 1);
    const float* aSrc = A + (size_t)mrow * lda + kOff + akq;

    // B global->smem: k rows bk, bk+16 ; n-quad bnq
    const int bk  = tid >> 4;             // 0..15
    const int bnq = (tid & 15) << 2;      // 0..60
    const int bBytes = ((bN + bnq) < N) ? 16 : 0;   // zero-fill OOB columns
    const float* bSrc = B + (size_t)(kOff + bk) * N + bN + bnq;

    uint32_t aD0[NSTG], aD1[NSTG], bD0[NSTG], bD1[NSTG];
    #pragma unroll
    for (int s = 0; s < NSTG; ++s) {
        aD0[s] = smem_u32(&sm[s * A_STW + ar * 36 + akq]);
        aD1[s] = smem_u32(&sm[s * A_STW + ar * 36 + akq + 16]);
        bD0[s] = smem_u32(&sm[B_BASE + s * A_STW + bk * 72 + bnq]);
        bD1[s] = smem_u32(&sm[B_BASE + s * A_STW + (bk + 16) * 72 + bnq]);
    }

    const int T = kLen >> 5;

    // prologue: stages 0,1
    #pragma unroll
    for (int p = 0; p < 2; ++p) {
        const int ko = p << 5;
        cp16(aD0[p], aSrc + ko, 16);
        cp16(aD1[p], aSrc + ko + 16, 16);
        cp16(bD0[p], bSrc + (size_t)ko * N, bBytes);
        cp16(bD1[p], bSrc + (size_t)(ko + 16) * N, bBytes);
        cp_commit();
    }

    float acc[2][2][4] = {};

    int stage = 0;
    for (int tt = 0; tt < T; ++tt) {
        if (tt + 1 < T) { asm volatile("cp.async.wait_group 1;\n"); }
        else            { asm volatile("cp.async.wait_group 0;\n"); }
        __syncthreads();

        if (tt + 2 < T) {
            const int ns = (stage + 2 >= NSTG) ? stage + 2 - NSTG : stage + 2;
            const int ko = (tt + 2) << 5;
            cp16(aD0[ns], aSrc + ko, 16);
            cp16(aD1[ns], aSrc + ko + 16, 16);
            cp16(bD0[ns], bSrc + (size_t)ko * N, bBytes);
            cp16(bD1[ns], bSrc + (size_t)(ko + 16) * N, bBytes);
            cp_commit();
        }

        const uint32_t* smA = sm + stage * A_STW;
        const uint32_t* smB = sm + B_BASE + stage * A_STW;
        #pragma unroll
        for (int ks = 0; ks < 4; ++ks) {
            const int k0 = ks << 3;
            uint32_t af[2][4];
            #pragma unroll
            for (int i = 0; i < 2; ++i) {
                const int base = (wm + (i << 4) + g) * 36 + k0 + t;
                af[i][0] = smA[base];
                af[i][1] = smA[base + 8 * 36];
                af[i][2] = smA[base + 4];
                af[i][3] = smA[base + 8 * 36 + 4];
            }
            uint32_t bf[2][2];
            #pragma unroll
            for (int j = 0; j < 2; ++j) {
                const int bb = (k0 + t) * 72 + wn + (j << 3) + g;
                bf[j][0] = smB[bb];
                bf[j][1] = smB[bb + 4 * 72];
            }
            #pragma unroll
            for (int i = 0; i < 2; ++i)
                #pragma unroll
                for (int j = 0; j < 2; ++j)
                    mma_tf32(acc[i][j], af[i], bf[j]);
        }
        stage = (stage + 1 >= NSTG) ? 0 : stage + 1;
    }

    // epilogue
    #pragma unroll
    for (int i = 0; i < 2; ++i) {
        const int r0 = bM + wm + (i << 4) + g;
        const int r1 = r0 + 8;
        #pragma unroll
        for (int j = 0; j < 2; ++j) {
            const int col = bN + wn + (j << 3) + (t << 1);
            if (col >= N) continue;
            float b0v = 0.f, b1v = 0.f;
            if (addBias) {
                float2 bb = *(const float2*)(bias + col);
                b0v = bb.x; b1v = bb.y;
            }
            float c0 = acc[i][j][0] + b0v, c1 = acc[i][j][1] + b1v;
            float c2 = acc[i][j][2] + b0v, c3 = acc[i][j][3] + b1v;
            if (act) { c0 = gelu_f(c0); c1 = gelu_f(c1); c2 = gelu_f(c2); c3 = gelu_f(c3); }
            if (r0 < M)
                for (int rr = 0; rr < rep; ++rr)
                    *(float2*)(C + (size_t)(r0 * rep + rr) * ldc + col) = make_float2(c0, c1);
            if (r1 < M)
                for (int rr = 0; rr < rep; ++rr)
                    *(float2*)(C + (size_t)(r1 * rep + rr) * ldc + col) = make_float2(c2, c3);
        }
    }
}

// ---------------- GEMM wrappers ----------------
__global__ void __launch_bounds__(256) gemm_std(
    const float* __restrict__ A, const float* __restrict__ B,
    const float* __restrict__ bias, float* __restrict__ C,
    int M, int N, int K, int act)
{
    int bM = blockIdx.y * GBM;
    if (bM >= M) return;
    gemm_core(A, B, bias, C, M, N, K, 0, K, bM, blockIdx.x * GBN, act, 1, N, 1);
}

__global__ void __launch_bounds__(256) gemm_splitk(
    const float* __restrict__ A, const float* __restrict__ B,
    float* __restrict__ C, int M, int N, int K, int sk)
{
    int bM = blockIdx.y * GBM;
    if (bM >= M) return;
    int z = blockIdx.z;
    gemm_core(A, B, nullptr, C + (size_t)z * M * N, M, N, K, z * sk, sk,
              bM, blockIdx.x * GBN, 0, 0, N, 1);
}

__constant__ int c_Ms[3]  = {500, 250, 125};
__constant__ int c_ro[3]  = {0, 500, 750};
__constant__ int c_sc[3]  = {1, 2, 4};

__global__ void __launch_bounds__(256) gemm_qkv(
    const float* __restrict__ h, const float* __restrict__ pool,
    const float* __restrict__ Wq, const float* __restrict__ Wk, const float* __restrict__ Wv,
    const float* __restrict__ bq, const float* __restrict__ bk, const float* __restrict__ bv,
    float* __restrict__ q, float* __restrict__ k, float* __restrict__ v)
{
    int z = blockIdx.z;
    int si = z / 3, which = z - si * 3;
    int M = c_Ms[si];
    int bM = blockIdx.y * GBM;
    if (bM >= M) return;
    const float* A = (si == 0) ? h : (pool + (si == 2 ? 250 * DMODEL : 0));
    const float* W = (which == 0) ? Wq : (which == 1) ? Wk : Wv;
    const float* bb = (which == 0) ? bq : (which == 1) ? bk : bv;
    float* Cb = (which == 0) ? q : (which == 1) ? k : v;
    gemm_core(A, W + (size_t)si * DMODEL * QKVD, bb + (size_t)si * QKVD,
              Cb + (size_t)c_ro[si] * QKVD, M, QKVD, DMODEL, 0, DMODEL,
              bM, blockIdx.x * GBN, 0, 1, QKVD, 1);
}

// Wo with fused upsample+concat: writes directly into cat buffer.
// K=160 is not a multiple of 32, so pass kLen=160 rounded: use 160 = 5*32 ✓
__global__ void __launch_bounds__(256) gemm_wo(
    const float* __restrict__ o, const float* __restrict__ Wo,
    const float* __restrict__ bo, float* __restrict__ cat)
{
    int si = blockIdx.z;
    int M = c_Ms[si];
    int bM = blockIdx.y * GBM;
    if (bM >= M) return;
    gemm_core(o + (size_t)c_ro[si] * QKVD, Wo + (size_t)si * QKVD * DMODEL,
              bo + (size_t)si * DMODEL, cat + (size_t)si * DMODEL,
              M, DMODEL, QKVD, 0, QKVD, bM, blockIdx.x * GBN, 0, 1,
              CATD, c_sc[si]);
}

// ---------------- small kernels ----------------
__global__ void colsum_kernel(const float* __restrict__ W, float* __restrict__ cs) {
    int d = threadIdx.x;
    float s = 0.f;
    #pragma unroll 4
    for (int p = 0; p < 100; p++) s += W[p * DMODEL + d];
    cs[d] = s;
}

__global__ void init_h_kernel(const float* __restrict__ cs, const float* __restrict__ ln_in_b,
                              const float* __restrict__ patch_b, const float* __restrict__ pos,
                              float* __restrict__ h) {
    int n = blockIdx.x, d = threadIdx.x;
    h[n * DMODEL + d] = ln_in_b[0] * cs[d] + patch_b[d] + pos[n * DMODEL + d];
}

__global__ void pool_kernel(const float* __restrict__ h, float* __restrict__ p) {
    int i = blockIdx.x, d = threadIdx.x;
    if (i < 250) {
        p[i * DMODEL + d] = 0.5f * (h[(2 * i) * DMODEL + d] + h[(2 * i + 1) * DMODEL + d]);
    } else {
        int j = i - 250;
        p[i * DMODEL + d] = 0.25f * (h[(4 * j) * DMODEL + d] + h[(4 * j + 1) * DMODEL + d] +
                                     h[(4 * j + 2) * DMODEL + d] + h[(4 * j + 3) * DMODEL + d]);
    }
}

// ---------------- attention: block per (scale, head, 8 queries) ----------------
__global__ void __launch_bounds__(256) attn_kernel(
    const float* __restrict__ q, const float* __restrict__ k,
    const float* __restrict__ v, float* __restrict__ o)
{
    __shared__ float Ks[32][34];
    __shared__ float Vs[32][34];
    __shared__ float OS[8][32][34];

    const int b = blockIdx.x;
    int Ns, ro, h, qg;
    if (b < 315)      { Ns = 500; ro = 0;   h = b / 63;  qg = b % 63; }
    else if (b < 475) { int c = b - 315; Ns = 250; ro = 500; h = c / 32; qg = c % 32; }
    else              { int c = b - 475; Ns = 125; ro = 750; h = c / 16; qg = c % 16; }

    const int wid = threadIdx.x >> 5;
    const int lane = threadIdx.x & 31;
    const int n = qg * 8 + wid;
    const bool valid = n < Ns;
    const int nq = valid ? n : (Ns - 1);
    const float scale = 0.1767766952966369f;  // 1/sqrt(32)

    float2 qr[16];
    {
        const float2* qp = (const float2*)(q + (size_t)(ro + nq) * QKVD + h * KDIM);
        #pragma unroll
        for (int i = 0; i < 16; i++) {
            float2 tq = qp[i];
            qr[i] = make_float2(tq.x * scale, tq.y * scale);
        }
    }

    float mmax = -INFINITY, ssum = 0.f;
    float oa[32];
    #pragma unroll
    for (int d = 0; d < 32; d++) oa[d] = 0.f;

    const int nt = (Ns + 31) >> 5;
    for (int tt = 0; tt < nt; tt++) {
        const int kt = tt << 5;
        {
            const int m = threadIdx.x >> 3;
            const int dq = (threadIdx.x & 7) << 2;
            const int row = min(kt + m, Ns - 1);
            const float4 kk = *(const float4*)(k + (size_t)(ro + row) * QKVD + h * KDIM + dq);
            const float4 vv = *(const float4*)(v + (size_t)(ro + row) * QKVD + h * KDIM + dq);
            *(float2*)&Ks[m][dq]     = make_float2(kk.x, kk.y);
            *(float2*)&Ks[m][dq + 2] = make_float2(kk.z, kk.w);
            *(float2*)&Vs[m][dq]     = make_float2(vv.x, vv.y);
            *(float2*)&Vs[m][dq + 2] = make_float2(vv.z, vv.w);
        }
        __syncthreads();

        float s0 = 0.f, s1 = 0.f;
        #pragma unroll
        for (int i = 0; i < 16; i++) {
            float2 kk = *(const float2*)&Ks[lane][2 * i];
            s0 = fmaf(qr[i].x, kk.x, s0);
            s1 = fmaf(qr[i].y, kk.y, s1);
        }
        float s = s0 + s1;
        if (kt + lane >= Ns) s = -INFINITY;

        float nm = fmaxf(mmax, s);
        float corr = __expf(mmax - nm);
        float p = __expf(s - nm);
        ssum = ssum * corr + p;
        #pragma unroll
        for (int i = 0; i < 16; i++) {
            float2 vv = *(const float2*)&Vs[lane][2 * i];
            oa[2 * i]     = oa[2 * i]     * corr + p * vv.x;
            oa[2 * i + 1] = oa[2 * i + 1] * corr + p * vv.y;
        }
        mmax = nm;
        __syncthreads();
    }

    float gm = mmax;
    #pragma unroll
    for (int off = 16; off; off >>= 1) gm = fmaxf(gm, __shfl_xor_sync(0xffffffffu, gm, off));
    float c = __expf(mmax - gm);
    float ss = ssum * c;
    #pragma unroll
    for (int off = 16; off; off >>= 1) ss += __shfl_xor_sync(0xffffffffu, ss, off);

    #pragma unroll
    for (int i = 0; i < 16; i++)
        *(float2*)&OS[wid][lane][2 * i] = make_float2(oa[2 * i] * c, oa[2 * i + 1] * c);
    __syncwarp();

    float accd = 0.f;
    #pragma unroll
    for (int m = 0; m < 32; m++) accd += OS[wid][m][lane];
    if (valid)
        o[(size_t)(ro + n) * QKVD + h * KDIM + lane] = accd / ss;
}

// h[n,:] = LayerNorm(h[n,:] + bias + sum_{s<S} part[s][n,:]) * g + b
__global__ void reduce_add_ln_kernel(const float* __restrict__ part, int S,
                                     const float* __restrict__ bias,
                                     float* __restrict__ h,
                                     const float* __restrict__ g,
                                     const float* __restrict__ b) {
    int n = blockIdx.x, t = threadIdx.x;
    __shared__ float red[8];
    __shared__ float stat;
    float v0 = h[n * DMODEL + t]       + bias[t];
    float v1 = h[n * DMODEL + t + 256] + bias[t + 256];
    for (int s = 0; s < S; s++) {
        v0 += part[(size_t)s * NPATCH * DMODEL + n * DMODEL + t];
        v1 += part[(size_t)s * NPATCH * DMODEL + n * DMODEL + t + 256];
    }

    float s = v0 + v1;
    #pragma unroll
    for (int o = 16; o; o >>= 1) s += __shfl_xor_sync(0xffffffffu, s, o);
    if ((t & 31) == 0) red[t >> 5] = s;
    __syncthreads();
    if (t < 32) {
        float x = (t < 8) ? red[t] : 0.f;
        #pragma unroll
        for (int o = 4; o; o >>= 1) x += __shfl_xor_sync(0xffffffffu, x, o);
        if (t == 0) stat = x / (float)DMODEL;
    }
    __syncthreads();
    float mean = stat;
    float dd0 = v0 - mean, dd1 = v1 - mean;

    __syncthreads();
    float vs = dd0 * dd0 + dd1 * dd1;
    #pragma unroll
    for (int o = 16; o; o >>= 1) vs += __shfl_xor_sync(0xffffffffu, vs, o);
    if ((t & 31) == 0) red[t >> 5] = vs;
    __syncthreads();
    if (t < 32) {
        float x = (t < 8) ? red[t] : 0.f;
        #pragma unroll
        for (int o = 4; o; o >>= 1) x += __shfl_xor_sync(0xffffffffu, x, o);
        if (t == 0) stat = rsqrtf(x / (float)DMODEL + LN_EPS);
    }
    __syncthreads();
    float rstd = stat;
    h[n * DMODEL + t]       = dd0 * rstd * g[t]       + b[t];
    h[n * DMODEL + t + 256] = dd1 * rstd * g[t + 256] + b[t + 256];
}

// fused global-mean-pool + head + softmax + broadcast
__global__ void head_kernel(const float* __restrict__ h, const float* __restrict__ W,
                            const float* __restrict__ b, float* __restrict__ out) {
    __shared__ float gs[DMODEL];
    __shared__ float red[8];
    __shared__ float stat;
    int t = threadIdx.x;  // 256
    {
        float s0 = 0.f, s1 = 0.f;
        for (int n = 0; n < NPATCH; n++) {
            s0 += h[n * DMODEL + t];
            s1 += h[n * DMODEL + t + 256];
        }
        gs[t] = s0 / (float)NPATCH;
        gs[t + 256] = s1 / (float)NPATCH;
    }
    __syncthreads();
    float acc = b[t];
    #pragma unroll 4
    for (int d = 0; d < DMODEL; d++) acc += gs[d] * W[d * NCLS + t];

    float m = acc;
    #pragma unroll
    for (int o = 16; o; o >>= 1) m = fmaxf(m, __shfl_xor_sync(0xffffffffu, m, o));
    if ((t & 31) == 0) red[t >> 5] = m;
    __syncthreads();
    if (t < 32) {
        float x = (t < 8) ? red[t] : -INFINITY;
        #pragma unroll
        for (int o = 4; o; o >>= 1) x = fmaxf(x, __shfl_xor_sync(0xffffffffu, x, o));
        if (t == 0) stat = x;
    }
    __syncthreads();
    float e = expf(acc - stat);
    __syncthreads();
    float s = e;
    #pragma unroll
    for (int o = 16; o; o >>= 1) s += __shfl_xor_sync(0xffffffffu, s, o);
    if ((t & 31) == 0) red[t >> 5] = s;
    __syncthreads();
    if (t < 32) {
        float x = (t < 8) ? red[t] : 0.f;
        #pragma unroll
        for (int o = 4; o; o >>= 1) x += __shfl_xor_sync(0xffffffffu, x, o);
        if (t == 0) stat = x;
    }
    __syncthreads();
    float p = e / stat;
    for (int bb = 0; bb < NBATCH; bb++) out[bb * NCLS + t] = p;
}

// ---------------- host launcher ----------------
extern "C" void kernel_launch(void* const* d_in, const int* in_sizes, int n_in,
                              void* d_out, int out_size) {
    const float* ln_in_b = (const float*)d_in[2];
    const float* patch_W = (const float*)d_in[3];
    const float* patch_b = (const float*)d_in[4];
    const float* pos_emb = (const float*)d_in[5];
    const float* Wq = (const float*)d_in[6];
    const float* bq = (const float*)d_in[7];
    const float* Wk = (const float*)d_in[8];
    const float* bk = (const float*)d_in[9];
    const float* Wv = (const float*)d_in[10];
    const float* bv = (const float*)d_in[11];
    const float* Wo = (const float*)d_in[12];
    const float* bo = (const float*)d_in[13];
    const float* Wc = (const float*)d_in[14];
    const float* bc = (const float*)d_in[15];
    const float* ln1_g = (const float*)d_in[16];
    const float* ln1_b = (const float*)d_in[17];
    const float* W1 = (const float*)d_in[18];
    const float* b1 = (const float*)d_in[19];
    const float* W2 = (const float*)d_in[20];
    const float* b2 = (const float*)d_in[21];
    const float* ln2_g = (const float*)d_in[22];
    const float* ln2_b = (const float*)d_in[23];
    const float* head_W = (const float*)d_in[24];
    const float* head_b = (const float*)d_in[25];
    float* out = (float*)d_out;

    static bool attrDone = false;
    if (!attrDone) {
        cudaFuncSetAttribute(gemm_std, cudaFuncAttributeMaxDynamicSharedMemorySize, SMEMB);
        cudaFuncSetAttribute(gemm_splitk, cudaFuncAttributeMaxDynamicSharedMemorySize, SMEMB);
        cudaFuncSetAttribute(gemm_qkv, cudaFuncAttributeMaxDynamicSharedMemorySize, SMEMB);
        cudaFuncSetAttribute(gemm_wo, cudaFuncAttributeMaxDynamicSharedMemorySize, SMEMB);
        attrDone = true;
    }

    float *hp, *pp, *qp, *kp, *vp, *op, *catp, *ffp, *partp, *csp;
    cudaGetSymbolAddress((void**)&hp,  d_h);
    cudaGetSymbolAddress((void**)&pp,  d_pool);
    cudaGetSymbolAddress((void**)&qp,  d_q);
    cudaGetSymbolAddress((void**)&kp,  d_k);
    cudaGetSymbolAddress((void**)&vp,  d_v);
    cudaGetSymbolAddress((void**)&op,  d_o);
    cudaGetSymbolAddress((void**)&catp, d_cat);
    cudaGetSymbolAddress((void**)&ffp, d_ff);
    cudaGetSymbolAddress((void**)&partp, d_part);
    cudaGetSymbolAddress((void**)&csp, d_cs);

    colsum_kernel<<<1, DMODEL>>>(patch_W, csp);
    init_h_kernel<<<NPATCH, DMODEL>>>(csp, ln_in_b, patch_b, pos_emb, hp);

    for (int l = 0; l < NLAYER; l++) {
        size_t wqkv = (size_t)l * 3 * DMODEL * QKVD;
        size_t bqkv = (size_t)l * 3 * QKVD;
        size_t wwo  = (size_t)l * 3 * QKVD * DMODEL;
        size_t bwo  = (size_t)l * 3 * DMODEL;

        pool_kernel<<<375, DMODEL>>>(hp, pp);
        gemm_qkv<<<dim3(3, 8, 9), 256, SMEMB>>>(hp, pp,
            Wq + wqkv, Wk + wqkv, Wv + wqkv, bq + bqkv, bk + bqkv, bv + bqkv,
            qp, kp, vp);
        attn_kernel<<<555, 256>>>(qp, kp, vp, op);
        gemm_wo<<<dim3(8, 8, 3), 256, SMEMB>>>(op, Wo + wwo, bo + bwo, catp);

        // combine: split-K 6x256 -> partials -> fused reduce+bias+residual+LN
        gemm_splitk<<<dim3(8, 8, 6), 256, SMEMB>>>(catp, Wc + (size_t)l * CATD * DMODEL,
                                                   partp, NPATCH, DMODEL, CATD, 256);
        reduce_add_ln_kernel<<<NPATCH, 256>>>(partp, 6, bc + (size_t)l * DMODEL, hp,
                                              ln1_g + l * DMODEL, ln1_b + l * DMODEL);

        // FFN
        gemm_std<<<dim3(32, 8), 256, SMEMB>>>(hp, W1 + (size_t)l * DMODEL * FFD,
                                              b1 + (size_t)l * FFD, ffp,
                                              NPATCH, FFD, DMODEL, 1);
        gemm_splitk<<<dim3(8, 8, 8), 256, SMEMB>>>(ffp, W2 + (size_t)l * FFD * DMODEL,
                                                   partp, NPATCH, DMODEL, FFD, 256);
        reduce_add_ln_kernel<<<NPATCH, 256>>>(partp, 8, b2 + (size_t)l * DMODEL, hp,
                                              ln2_g + l * DMODEL, ln2_b + l * DMODEL);
    }

    head_kernel<<<1, NCLS>>>(hp, head_W, head_b, out);
}

// round 8
// speedup vs baseline: 16.0794x; 1.0246x over previous
#include <cuda_runtime.h>
#include <cstdint>
#include <math.h>

// ---------------- problem constants ----------------
#define NPATCH 500
#define DMODEL 512
#define NHS    5
#define KDIM   32
#define QKVD   160
#define CATD   1536
#define FFD    2048
#define NLAYER 6
#define NBATCH 32
#define NCLS   256
#define LN_EPS 1e-3f
#define RTOT 875     // rows: scale1 [0,500), scale2 [500,750), scale4 [750,875)

#define GBM 64
#define GBN 64
#define GBK 32
#define NSTG 3
// dynamic smem layout (uint32 words):
//   As(s,m,k) = sm[s*2304 + m*36 + k]          (64 x pad36)
//   Bs(s,k,n) = sm[6912 + s*2304 + k*72 + n]   (32 x pad72)
#define A_STW 2304
#define B_BASE 6912
#define SMEMB 55296

// ---------------- scratch ----------------
__device__ float d_h   [NPATCH * DMODEL];
__device__ float d_pool[375 * DMODEL];
__device__ float d_q   [RTOT * QKVD];
__device__ float d_k   [RTOT * QKVD];
__device__ float d_v   [RTOT * QKVD];
__device__ float d_o   [RTOT * QKVD];
__device__ float d_cat [NPATCH * CATD];
__device__ float d_ff  [NPATCH * FFD];
__device__ float d_part[8 * NPATCH * DMODEL];
__device__ float d_qkvp[6 * RTOT * QKVD];      // [s*3+which][row][c]
__device__ float d_wop [6 * RTOT * DMODEL];    // [s*3+si][row][d]
__device__ float d_cs  [DMODEL];

// ---------------- helpers ----------------
__device__ __forceinline__ uint32_t smem_u32(const void* p) {
    return (uint32_t)__cvta_generic_to_shared(p);
}
__device__ __forceinline__ void cp16(uint32_t dst, const void* src, int sbytes) {
    asm volatile("cp.async.cg.shared.global [%0], [%1], 16, %2;\n"
                 :: "r"(dst), "l"(src), "r"(sbytes));
}
__device__ __forceinline__ void cp_commit() { asm volatile("cp.async.commit_group;\n"); }
__device__ __forceinline__ void mma_tf32(float* c, const uint32_t* a, const uint32_t* b) {
    asm volatile(
        "mma.sync.aligned.m16n8k8.row.col.f32.tf32.tf32.f32 "
        "{%0,%1,%2,%3}, {%4,%5,%6,%7}, {%8,%9}, {%0,%1,%2,%3};"
        : "+f"(c[0]), "+f"(c[1]), "+f"(c[2]), "+f"(c[3])
        : "r"(a[0]), "r"(a[1]), "r"(a[2]), "r"(a[3]), "r"(b[0]), "r"(b[1]));
}
__device__ __forceinline__ void ldsm4(uint32_t& d0, uint32_t& d1, uint32_t& d2, uint32_t& d3,
                                      uint32_t addr) {
    asm volatile("ldmatrix.sync.aligned.m8n8.x4.shared.b16 {%0,%1,%2,%3}, [%4];"
                 : "=r"(d0), "=r"(d1), "=r"(d2), "=r"(d3) : "r"(addr));
}
__device__ __forceinline__ float gelu_f(float x) {
    return 0.5f * x * (1.f + erff(x * 0.70710678118654752f));
}

// ---------------- core GEMM tile (tf32 MMA + ldmatrix A, 3-stage cp.async) ----
// 256 thr, block 64x64xGBK32, 8 warps (2m x 4n), warp tile 32x16.
// A row-major (lda), B row-major (N). kLen % 32 == 0, N % 4 == 0.
__device__ __forceinline__ void gemm_core(
    const float* __restrict__ A, const float* __restrict__ B,
    const float* __restrict__ bias, float* __restrict__ C,
    int M, int N, int lda, int kOff, int kLen,
    int bM, int bN, int act, int addBias)
{
    extern __shared__ uint32_t sm[];

    const int tid  = threadIdx.x;
    const int lane = tid & 31;
    const int warp = tid >> 5;
    const int wm = (warp & 1) << 5;       // 0,32
    const int wn = (warp >> 1) << 4;      // 0,16,32,48
    const int g = lane >> 2;              // 0..7
    const int t = lane & 3;               // 0..3

    // ldmatrix per-thread source row/col inside warp's A tile
    const int lrow = lane & 7;
    const int mat  = lane >> 3;           // 0..3
    int aoffw[2];                          // word offsets (without stage/k0)
    #pragma unroll
    for (int i = 0; i < 2; ++i)
        aoffw[i] = (wm + (i << 4) + ((mat & 1) << 3) + lrow) * 36 + ((mat >> 1) << 2);
    const uint32_t smb = smem_u32(sm);

    // A global->smem: row ar (0..63), k quads akq, akq+16
    const int ar  = tid >> 2;             // 0..63
    const int akq = (tid & 3) << 2;       // 0,4,8,12
    const int mrow = min(bM + ar, M - 1);
    const float* aSrc = A + (size_t)mrow * lda + kOff + akq;

    // B global->smem: k rows bk, bk+16 ; n-quad bnq
    const int bk  = tid >> 4;             // 0..15
    const int bnq = (tid & 15) << 2;      // 0..60
    const int bBytes = ((bN + bnq) < N) ? 16 : 0;   // zero-fill OOB columns
    const float* bSrc = B + (size_t)(kOff + bk) * N + bN + bnq;

    uint32_t aD0[NSTG], aD1[NSTG], bD0[NSTG], bD1[NSTG];
    #pragma unroll
    for (int s = 0; s < NSTG; ++s) {
        aD0[s] = smem_u32(&sm[s * A_STW + ar * 36 + akq]);
        aD1[s] = smem_u32(&sm[s * A_STW + ar * 36 + akq + 16]);
        bD0[s] = smem_u32(&sm[B_BASE + s * A_STW + bk * 72 + bnq]);
        bD1[s] = smem_u32(&sm[B_BASE + s * A_STW + (bk + 16) * 72 + bnq]);
    }

    const int T = kLen >> 5;

    // prologue: stages 0,1
    #pragma unroll
    for (int p = 0; p < 2; ++p) {
        const int ko = p << 5;
        cp16(aD0[p], aSrc + ko, 16);
        cp16(aD1[p], aSrc + ko + 16, 16);
        cp16(bD0[p], bSrc + (size_t)ko * N, bBytes);
        cp16(bD1[p], bSrc + (size_t)(ko + 16) * N, bBytes);
        cp_commit();
    }

    float acc[2][2][4] = {};

    int stage = 0;
    for (int tt = 0; tt < T; ++tt) {
        if (tt + 1 < T) { asm volatile("cp.async.wait_group 1;\n"); }
        else            { asm volatile("cp.async.wait_group 0;\n"); }
        __syncthreads();

        if (tt + 2 < T) {
            const int ns = (stage + 2 >= NSTG) ? stage + 2 - NSTG : stage + 2;
            const int ko = (tt + 2) << 5;
            cp16(aD0[ns], aSrc + ko, 16);
            cp16(aD1[ns], aSrc + ko + 16, 16);
            cp16(bD0[ns], bSrc + (size_t)ko * N, bBytes);
            cp16(bD1[ns], bSrc + (size_t)(ko + 16) * N, bBytes);
            cp_commit();
        }

        const uint32_t aStage = smb + ((stage * A_STW) << 2);
        const uint32_t* smB = sm + B_BASE + stage * A_STW;
        #pragma unroll
        for (int ks = 0; ks < 4; ++ks) {
            const int k0 = ks << 3;
            uint32_t af[2][4];
            #pragma unroll
            for (int i = 0; i < 2; ++i)
                ldsm4(af[i][0], af[i][1], af[i][2], af[i][3],
                      aStage + ((aoffw[i] + k0) << 2));
            uint32_t bf[2][2];
            #pragma unroll
            for (int j = 0; j < 2; ++j) {
                const int bb = (k0 + t) * 72 + wn + (j << 3) + g;
                bf[j][0] = smB[bb];
                bf[j][1] = smB[bb + 4 * 72];
            }
            #pragma unroll
            for (int i = 0; i < 2; ++i)
                #pragma unroll
                for (int j = 0; j < 2; ++j)
                    mma_tf32(acc[i][j], af[i], bf[j]);
        }
        stage = (stage + 1 >= NSTG) ? 0 : stage + 1;
    }

    // epilogue
    #pragma unroll
    for (int i = 0; i < 2; ++i) {
        const int r0 = bM + wm + (i << 4) + g;
        const int r1 = r0 + 8;
        #pragma unroll
        for (int j = 0; j < 2; ++j) {
            const int col = bN + wn + (j << 3) + (t << 1);
            if (col >= N) continue;
            float b0v = 0.f, b1v = 0.f;
            if (addBias) {
                float2 bb = *(const float2*)(bias + col);
                b0v = bb.x; b1v = bb.y;
            }
            float c0 = acc[i][j][0] + b0v, c1 = acc[i][j][1] + b1v;
            float c2 = acc[i][j][2] + b0v, c3 = acc[i][j][3] + b1v;
            if (act) { c0 = gelu_f(c0); c1 = gelu_f(c1); c2 = gelu_f(c2); c3 = gelu_f(c3); }
            if (r0 < M) *(float2*)(C + (size_t)r0 * N + col) = make_float2(c0, c1);
            if (r1 < M) *(float2*)(C + (size_t)r1 * N + col) = make_float2(c2, c3);
        }
    }
}

// ---------------- GEMM wrappers ----------------
__global__ void __launch_bounds__(256) gemm_std(
    const float* __restrict__ A, const float* __restrict__ B,
    const float* __restrict__ bias, float* __restrict__ C,
    int M, int N, int K, int act)
{
    int bM = blockIdx.y * GBM;
    if (bM >= M) return;
    gemm_core(A, B, bias, C, M, N, K, 0, K, bM, blockIdx.x * GBN, act, 1);
}

__global__ void __launch_bounds__(256) gemm_splitk(
    const float* __restrict__ A, const float* __restrict__ B,
    float* __restrict__ C, int M, int N, int K, int sk)
{
    int bM = blockIdx.y * GBM;
    if (bM >= M) return;
    int z = blockIdx.z;
    gemm_core(A, B, nullptr, C + (size_t)z * M * N, M, N, K, z * sk, sk,
              bM, blockIdx.x * GBN, 0, 0);
}

__constant__ int c_Ms[3]  = {500, 250, 125};
__constant__ int c_ro[3]  = {0, 500, 750};

// qkv split-K: z = s*9 + si*3 + which ; kOff = s*256, kLen = 256
__global__ void __launch_bounds__(256) gemm_qkv(
    const float* __restrict__ h, const float* __restrict__ pool,
    const float* __restrict__ Wq, const float* __restrict__ Wk, const float* __restrict__ Wv,
    float* __restrict__ P)
{
    int z = blockIdx.z;
    int s = z / 9, rem = z - s * 9;
    int si = rem / 3, which = rem - si * 3;
    int M = c_Ms[si];
    int bM = blockIdx.y * GBM;
    if (bM >= M) return;
    const float* A = (si == 0) ? h : (pool + (si == 2 ? 250 * DMODEL : 0));
    const float* W = (which == 0) ? Wq : (which == 1) ? Wk : Wv;
    float* Cb = P + ((size_t)(s * 3 + which) * RTOT + c_ro[si]) * QKVD;
    gemm_core(A, W + (size_t)si * DMODEL * QKVD, nullptr, Cb,
              M, QKVD, DMODEL, s * 256, 256, bM, blockIdx.x * GBN, 0, 0);
}

// q/k/v = P[s0]+P[s1]+bias ; grid (875,3) x 160 thr
__global__ void reduce_qkv(const float* __restrict__ P,
                           const float* __restrict__ bq, const float* __restrict__ bk,
                           const float* __restrict__ bv,
                           float* __restrict__ q, float* __restrict__ k,
                           float* __restrict__ v)
{
    int r = blockIdx.x, w = blockIdx.y, c = threadIdx.x;
    int si = (r < 500) ? 0 : (r < 750 ? 1 : 2);
    const float* bias = (w == 0) ? bq : (w == 1) ? bk : bv;
    float val = P[((size_t)(0 + w) * RTOT + r) * QKVD + c]
              + P[((size_t)(3 + w) * RTOT + r) * QKVD + c]
              + bias[si * QKVD + c];
    float* outp = (w == 0) ? q : (w == 1) ? k : v;
    outp[(size_t)r * QKVD + c] = val;
}

// wo split-K: z = s*3 + si ; split {0..96, 96..160}
__global__ void __launch_bounds__(256) gemm_wo(
    const float* __restrict__ o, const float* __restrict__ Wo,
    float* __restrict__ P)
{
    int z = blockIdx.z;
    int s = z / 3, si = z - s * 3;
    int M = c_Ms[si];
    int bM = blockIdx.y * GBM;
    if (bM >= M) return;
    int kOff = s ? 96 : 0;
    int kLen = s ? 64 : 96;
    float* Cb = P + ((size_t)(s * 3 + si) * RTOT + c_ro[si]) * DMODEL;
    gemm_core(o + (size_t)c_ro[si] * QKVD, Wo + (size_t)si * QKVD * DMODEL,
              nullptr, Cb, M, DMODEL, QKVD, kOff, kLen, bM, blockIdx.x * GBN, 0, 0);
}

// cat[n][si*512+d] = P[s0][si][src]+P[s1][si][src] + bo[si] ; grid 500 x 512
__global__ void reduce_wo_cat(const float* __restrict__ P, const float* __restrict__ bo,
                              float* __restrict__ cat)
{
    int n = blockIdx.x, d = threadIdx.x;
    #pragma unroll
    for (int si = 0; si < 3; ++si) {
        int src = c_ro[si] + (si == 0 ? n : (si == 1 ? (n >> 1) : (n >> 2)));
        float val = P[((size_t)(0 + si) * RTOT + src) * DMODEL + d]
                  + P[((size_t)(3 + si) * RTOT + src) * DMODEL + d]
                  + bo[si * DMODEL + d];
        cat[(size_t)n * CATD + si * DMODEL + d] = val;
    }
}

// ---------------- small kernels ----------------
__global__ void colsum_kernel(const float* __restrict__ W, float* __restrict__ cs) {
    int d = threadIdx.x;
    float s = 0.f;
    #pragma unroll 4
    for (int p = 0; p < 100; p++) s += W[p * DMODEL + d];
    cs[d] = s;
}

__global__ void init_h_kernel(const float* __restrict__ cs, const float* __restrict__ ln_in_b,
                              const float* __restrict__ patch_b, const float* __restrict__ pos,
                              float* __restrict__ h) {
    int n = blockIdx.x, d = threadIdx.x;
    h[n * DMODEL + d] = ln_in_b[0] * cs[d] + patch_b[d] + pos[n * DMODEL + d];
}

__global__ void pool_kernel(const float* __restrict__ h, float* __restrict__ p) {
    int i = blockIdx.x, d = threadIdx.x;
    if (i < 250) {
        p[i * DMODEL + d] = 0.5f * (h[(2 * i) * DMODEL + d] + h[(2 * i + 1) * DMODEL + d]);
    } else {
        int j = i - 250;
        p[i * DMODEL + d] = 0.25f * (h[(4 * j) * DMODEL + d] + h[(4 * j + 1) * DMODEL + d] +
                                     h[(4 * j + 2) * DMODEL + d] + h[(4 * j + 3) * DMODEL + d]);
    }
}

// ---------------- attention: block per (scale, head, 8 queries) ----------------
__global__ void __launch_bounds__(256) attn_kernel(
    const float* __restrict__ q, const float* __restrict__ k,
    const float* __restrict__ v, float* __restrict__ o)
{
    __shared__ float Ks[32][34];
    __shared__ float Vs[32][34];
    __shared__ float OS[8][32][34];

    const int b = blockIdx.x;
    int Ns, ro, h, qg;
    if (b < 315)      { Ns = 500; ro = 0;   h = b / 63;  qg = b % 63; }
    else if (b < 475) { int c = b - 315; Ns = 250; ro = 500; h = c / 32; qg = c % 32; }
    else              { int c = b - 475; Ns = 125; ro = 750; h = c / 16; qg = c % 16; }

    const int wid = threadIdx.x >> 5;
    const int lane = threadIdx.x & 31;
    const int n = qg * 8 + wid;
    const bool valid = n < Ns;
    const int nq = valid ? n : (Ns - 1);
    const float scale = 0.1767766952966369f;  // 1/sqrt(32)

    float2 qr[16];
    {
        const float2* qp = (const float2*)(q + (size_t)(ro + nq) * QKVD + h * KDIM);
        #pragma unroll
        for (int i = 0; i < 16; i++) {
            float2 tq = qp[i];
            qr[i] = make_float2(tq.x * scale, tq.y * scale);
        }
    }

    float mmax = -INFINITY, ssum = 0.f;
    float oa[32];
    #pragma unroll
    for (int d = 0; d < 32; d++) oa[d] = 0.f;

    const int nt = (Ns + 31) >> 5;
    for (int tt = 0; tt < nt; tt++) {
        const int kt = tt << 5;
        {
            const int m = threadIdx.x >> 3;
            const int dq = (threadIdx.x & 7) << 2;
            const int row = min(kt + m, Ns - 1);
            const float4 kk = *(const float4*)(k + (size_t)(ro + row) * QKVD + h * KDIM + dq);
            const float4 vv = *(const float4*)(v + (size_t)(ro + row) * QKVD + h * KDIM + dq);
            *(float2*)&Ks[m][dq]     = make_float2(kk.x, kk.y);
            *(float2*)&Ks[m][dq + 2] = make_float2(kk.z, kk.w);
            *(float2*)&Vs[m][dq]     = make_float2(vv.x, vv.y);
            *(float2*)&Vs[m][dq + 2] = make_float2(vv.z, vv.w);
        }
        __syncthreads();

        float s0 = 0.f, s1 = 0.f;
        #pragma unroll
        for (int i = 0; i < 16; i++) {
            float2 kk = *(const float2*)&Ks[lane][2 * i];
            s0 = fmaf(qr[i].x, kk.x, s0);
            s1 = fmaf(qr[i].y, kk.y, s1);
        }
        float s = s0 + s1;
        if (kt + lane >= Ns) s = -INFINITY;

        float nm = fmaxf(mmax, s);
        float corr = __expf(mmax - nm);
        float p = __expf(s - nm);
        ssum = ssum * corr + p;
        #pragma unroll
        for (int i = 0; i < 16; i++) {
            float2 vv = *(const float2*)&Vs[lane][2 * i];
            oa[2 * i]     = oa[2 * i]     * corr + p * vv.x;
            oa[2 * i + 1] = oa[2 * i + 1] * corr + p * vv.y;
        }
        mmax = nm;
        __syncthreads();
    }

    float gm = mmax;
    #pragma unroll
    for (int off = 16; off; off >>= 1) gm = fmaxf(gm, __shfl_xor_sync(0xffffffffu, gm, off));
    float c = __expf(mmax - gm);
    float ss = ssum * c;
    #pragma unroll
    for (int off = 16; off; off >>= 1) ss += __shfl_xor_sync(0xffffffffu, ss, off);

    #pragma unroll
    for (int i = 0; i < 16; i++)
        *(float2*)&OS[wid][lane][2 * i] = make_float2(oa[2 * i] * c, oa[2 * i + 1] * c);
    __syncwarp();

    float accd = 0.f;
    #pragma unroll
    for (int m = 0; m < 32; m++) accd += OS[wid][m][lane];
    if (valid)
        o[(size_t)(ro + n) * QKVD + h * KDIM + lane] = accd / ss;
}

// h[n,:] = LayerNorm(h[n,:] + bias + sum_{s<S} part[s][n,:]) * g + b
__global__ void reduce_add_ln_kernel(const float* __restrict__ part, int S,
                                     const float* __restrict__ bias,
                                     float* __restrict__ h,
                                     const float* __restrict__ g,
                                     const float* __restrict__ b) {
    int n = blockIdx.x, t = threadIdx.x;
    __shared__ float red[8];
    __shared__ float stat;
    float v0 = h[n * DMODEL + t]       + bias[t];
    float v1 = h[n * DMODEL + t + 256] + bias[t + 256];
    for (int s = 0; s < S; s++) {
        v0 += part[(size_t)s * NPATCH * DMODEL + n * DMODEL + t];
        v1 += part[(size_t)s * NPATCH * DMODEL + n * DMODEL + t + 256];
    }

    float s = v0 + v1;
    #pragma unroll
    for (int o = 16; o; o >>= 1) s += __shfl_xor_sync(0xffffffffu, s, o);
    if ((t & 31) == 0) red[t >> 5] = s;
    __syncthreads();
    if (t < 32) {
        float x = (t < 8) ? red[t] : 0.f;
        #pragma unroll
        for (int o = 4; o; o >>= 1) x += __shfl_xor_sync(0xffffffffu, x, o);
        if (t == 0) stat = x / (float)DMODEL;
    }
    __syncthreads();
    float mean = stat;
    float dd0 = v0 - mean, dd1 = v1 - mean;

    __syncthreads();
    float vs = dd0 * dd0 + dd1 * dd1;
    #pragma unroll
    for (int o = 16; o; o >>= 1) vs += __shfl_xor_sync(0xffffffffu, vs, o);
    if ((t & 31) == 0) red[t >> 5] = vs;
    __syncthreads();
    if (t < 32) {
        float x = (t < 8) ? red[t] : 0.f;
        #pragma unroll
        for (int o = 4; o; o >>= 1) x += __shfl_xor_sync(0xffffffffu, x, o);
        if (t == 0) stat = rsqrtf(x / (float)DMODEL + LN_EPS);
    }
    __syncthreads();
    float rstd = stat;
    h[n * DMODEL + t]       = dd0 * rstd * g[t]       + b[t];
    h[n * DMODEL + t + 256] = dd1 * rstd * g[t + 256] + b[t + 256];
}

// fused global-mean-pool + head + softmax + broadcast
__global__ void head_kernel(const float* __restrict__ h, const float* __restrict__ W,
                            const float* __restrict__ b, float* __restrict__ out) {
    __shared__ float gs[DMODEL];
    __shared__ float red[8];
    __shared__ float stat;
    int t = threadIdx.x;  // 256
    {
        float s0 = 0.f, s1 = 0.f;
        for (int n = 0; n < NPATCH; n++) {
            s0 += h[n * DMODEL + t];
            s1 += h[n * DMODEL + t + 256];
        }
        gs[t] = s0 / (float)NPATCH;
        gs[t + 256] = s1 / (float)NPATCH;
    }
    __syncthreads();
    float acc = b[t];
    #pragma unroll 4
    for (int d = 0; d < DMODEL; d++) acc += gs[d] * W[d * NCLS + t];

    float m = acc;
    #pragma unroll
    for (int o = 16; o; o >>= 1) m = fmaxf(m, __shfl_xor_sync(0xffffffffu, m, o));
    if ((t & 31) == 0) red[t >> 5] = m;
    __syncthreads();
    if (t < 32) {
        float x = (t < 8) ? red[t] : -INFINITY;
        #pragma unroll
        for (int o = 4; o; o >>= 1) x = fmaxf(x, __shfl_xor_sync(0xffffffffu, x, o));
        if (t == 0) stat = x;
    }
    __syncthreads();
    float e = expf(acc - stat);
    __syncthreads();
    float s = e;
    #pragma unroll
    for (int o = 16; o; o >>= 1) s += __shfl_xor_sync(0xffffffffu, s, o);
    if ((t & 31) == 0) red[t >> 5] = s;
    __syncthreads();
    if (t < 32) {
        float x = (t < 8) ? red[t] : 0.f;
        #pragma unroll
        for (int o = 4; o; o >>= 1) x += __shfl_xor_sync(0xffffffffu, x, o);
        if (t == 0) stat = x;
    }
    __syncthreads();
    float p = e / stat;
    for (int bb = 0; bb < NBATCH; bb++) out[bb * NCLS + t] = p;
}

// ---------------- host launcher ----------------
extern "C" void kernel_launch(void* const* d_in, const int* in_sizes, int n_in,
                              void* d_out, int out_size) {
    const float* ln_in_b = (const float*)d_in[2];
    const float* patch_W = (const float*)d_in[3];
    const float* patch_b = (const float*)d_in[4];
    const float* pos_emb = (const float*)d_in[5];
    const float* Wq = (const float*)d_in[6];
    const float* bq = (const float*)d_in[7];
    const float* Wk = (const float*)d_in[8];
    const float* bk = (const float*)d_in[9];
    const float* Wv = (const float*)d_in[10];
    const float* bv = (const float*)d_in[11];
    const float* Wo = (const float*)d_in[12];
    const float* bo = (const float*)d_in[13];
    const float* Wc = (const float*)d_in[14];
    const float* bc = (const float*)d_in[15];
    const float* ln1_g = (const float*)d_in[16];
    const float* ln1_b = (const float*)d_in[17];
    const float* W1 = (const float*)d_in[18];
    const float* b1 = (const float*)d_in[19];
    const float* W2 = (const float*)d_in[20];
    const float* b2 = (const float*)d_in[21];
    const float* ln2_g = (const float*)d_in[22];
    const float* ln2_b = (const float*)d_in[23];
    const float* head_W = (const float*)d_in[24];
    const float* head_b = (const float*)d_in[25];
    float* out = (float*)d_out;

    static bool attrDone = false;
    if (!attrDone) {
        cudaFuncSetAttribute(gemm_std, cudaFuncAttributeMaxDynamicSharedMemorySize, SMEMB);
        cudaFuncSetAttribute(gemm_splitk, cudaFuncAttributeMaxDynamicSharedMemorySize, SMEMB);
        cudaFuncSetAttribute(gemm_qkv, cudaFuncAttributeMaxDynamicSharedMemorySize, SMEMB);
        cudaFuncSetAttribute(gemm_wo, cudaFuncAttributeMaxDynamicSharedMemorySize, SMEMB);
        attrDone = true;
    }

    float *hp, *pp, *qp, *kp, *vp, *op, *catp, *ffp, *partp, *csp, *qkvpp, *wopp;
    cudaGetSymbolAddress((void**)&hp,  d_h);
    cudaGetSymbolAddress((void**)&pp,  d_pool);
    cudaGetSymbolAddress((void**)&qp,  d_q);
    cudaGetSymbolAddress((void**)&kp,  d_k);
    cudaGetSymbolAddress((void**)&vp,  d_v);
    cudaGetSymbolAddress((void**)&op,  d_o);
    cudaGetSymbolAddress((void**)&catp, d_cat);
    cudaGetSymbolAddress((void**)&ffp, d_ff);
    cudaGetSymbolAddress((void**)&partp, d_part);
    cudaGetSymbolAddress((void**)&csp, d_cs);
    cudaGetSymbolAddress((void**)&qkvpp, d_qkvp);
    cudaGetSymbolAddress((void**)&wopp, d_wop);

    colsum_kernel<<<1, DMODEL>>>(patch_W, csp);
    init_h_kernel<<<NPATCH, DMODEL>>>(csp, ln_in_b, patch_b, pos_emb, hp);

    for (int l = 0; l < NLAYER; l++) {
        size_t wqkv = (size_t)l * 3 * DMODEL * QKVD;
        size_t bqkv = (size_t)l * 3 * QKVD;
        size_t wwo  = (size_t)l * 3 * QKVD * DMODEL;
        size_t bwo  = (size_t)l * 3 * DMODEL;

        pool_kernel<<<375, DMODEL>>>(hp, pp);
        gemm_qkv<<<dim3(3, 8, 18), 256, SMEMB>>>(hp, pp,
            Wq + wqkv, Wk + wqkv, Wv + wqkv, qkvpp);
        reduce_qkv<<<dim3(RTOT, 3), QKVD>>>(qkvpp, bq + bqkv, bk + bqkv, bv + bqkv,
                                            qp, kp, vp);
        attn_kernel<<<555, 256>>>(qp, kp, vp, op);
        gemm_wo<<<dim3(8, 8, 6), 256, SMEMB>>>(op, Wo + wwo, wopp);
        reduce_wo_cat<<<NPATCH, DMODEL>>>(wopp, bo + bwo, catp);

        // combine: split-K 6x256 -> partials -> fused reduce+bias+residual+LN
        gemm_splitk<<<dim3(8, 8, 6), 256, SMEMB>>>(catp, Wc + (size_t)l * CATD * DMODEL,
                                                   partp, NPATCH, DMODEL, CATD, 256);
        reduce_add_ln_kernel<<<NPATCH, 256>>>(partp, 6, bc + (size_t)l * DMODEL, hp,
                                              ln1_g + l * DMODEL, ln1_b + l * DMODEL);

        // FFN
        gemm_std<<<dim3(32, 8), 256, SMEMB>>>(hp, W1 + (size_t)l * DMODEL * FFD,
                                              b1 + (size_t)l * FFD, ffp,
                                              NPATCH, FFD, DMODEL, 1);
        gemm_splitk<<<dim3(8, 8, 8), 256, SMEMB>>>(ffp, W2 + (size_t)l * FFD * DMODEL,
                                                   partp, NPATCH, DMODEL, FFD, 256);
        reduce_add_ln_kernel<<<NPATCH, 256>>>(partp, 8, b2 + (size_t)l * DMODEL, hp,
                                              ln2_g + l * DMODEL, ln2_b + l * DMODEL);
    }

    head_kernel<<<1, NCLS>>>(hp, head_W, head_b, out);
}